// round 9
// baseline (speedup 1.0000x reference)
#include <cuda_runtime.h>
#include <cuda_fp16.h>

#define HID 128
#define NS  12
#define PAD 132          // weight row pitch (elements)
#define NW  28           // warps per CTA
#define NB  4            // batch elements per warp-task
#define THREADS (NW*32)
#define GRID 148

typedef unsigned long long ull;

// ---- shared memory layout (float offsets) ----
#define OW0   0                      // W0^T  [12][132] fp32
#define OCEN  1584                   // 12 (pad 16)
#define OINV  1600                   // 12 (pad 16)
#define OW1H  1616                   // W1^T  [128][132] fp16  (8448 floats)
#define OW2H  10064                  // W2^T  [128][132] fp16  (8448 floats)
#define OWARP 18512
#define WSTRIDE 768                  // BigA 512 + V1h 256
#define SMEM_FLOATS (OWARP + NW*WSTRIDE)   // 40016 floats = 160064 B

__device__ float g_R3[HID];
__device__ float g_c3;

__global__ void init_kernel(const float* __restrict__ W3, const float* __restrict__ b3,
                            const float* __restrict__ Wout, const float* __restrict__ bout)
{
    int h = threadIdx.x;  // 0..127
    float acc = 0.f;
    for (int j = 0; j < HID; ++j) acc = fmaf(Wout[j], W3[j*HID + h], acc);
    g_R3[h] = acc;
    if (h == 0) {
        float c = bout[0];
        for (int j = 0; j < HID; ++j) c = fmaf(Wout[j], b3[j], c);
        g_c3 = c;
    }
}

// ---- packed f32x2 helpers ----
__device__ __forceinline__ ull ffma2(ull a, ull b, ull c)
{
    ull d;
    asm("fma.rn.f32x2 %0, %1, %2, %3;" : "=l"(d) : "l"(a), "l"(b), "l"(c));
    return d;
}
__device__ __forceinline__ ull pack2(float lo, float hi)
{
    ull d; asm("mov.b64 %0, {%1, %2};" : "=l"(d) : "f"(lo), "f"(hi)); return d;
}
__device__ __forceinline__ void unpack2(ull v, float& lo, float& hi)
{
    asm("mov.b64 {%0, %1}, %2;" : "=f"(lo), "=f"(hi) : "l"(v));
}
__device__ __forceinline__ ull shflx(ull v, int src)
{
    return __shfl_sync(0xffffffffu, v, src);
}

// Fast tanh: 1 - 2/(e^{2x}+1).
__device__ __forceinline__ float ftanh(float x)
{
    float e = __expf(2.0f * x);
    return 1.0f - __fdividef(2.0f, e + 1.0f);
}

// ---- swizzles ----
// BigA: [128][4] fp32 (16B rows). Conflict-free for fwd store h=4l+j and
// bwd store h=l+32m (verified per 8-lane phase).
__device__ __forceinline__ int phys4(int h)  { return h ^ ((h >> 3) & 3); }
// V1h: [128][4] fp16 (8B rows). Conflict-free for write h=4l+j and read
// h=l+32m (verified per 16-lane phase).
__device__ __forceinline__ int phys16(int h) { return h ^ ((h >> 4) & 3); }

__device__ __forceinline__ void store4(float* buf, int h, const float t[4])
{
    *(float4*)(buf + phys4(h)*4) = make_float4(t[0], t[1], t[2], t[3]);
}

// unpack uint2 of half2s -> 4 floats
__device__ __forceinline__ void h4_to_f4(uint2 u, float w[4])
{
    float2 f01 = __half22float2(*(__half2*)&u.x);
    float2 f23 = __half22float2(*(__half2*)&u.y);
    w[0] = f01.x; w[1] = f01.y; w[2] = f23.x; w[3] = f23.y;
}

// Forward matvec, fp16 weights, 4 batches (2 f32x2 pairs):
//   z[j][pp] = bias[4l+j] + sum_k Wt[k][4l+j]*in[k][pp]
__device__ __forceinline__ void fwd2h(const __half* __restrict__ Wh,
                                      const float* __restrict__ biasg,
                                      const float* __restrict__ inq,
                                      ull z[4][2], int l)
{
    float4 bb = *(const float4*)&biasg[4*l];
    float bj[4] = {bb.x, bb.y, bb.z, bb.w};
#pragma unroll
    for (int j = 0; j < 4; ++j) {
        ull b2 = pack2(bj[j], bj[j]);
        z[j][0] = b2; z[j][1] = b2;
    }

#pragma unroll 4
    for (int k = 0; k < HID; ++k) {
        uint2 u = *(const uint2*)&Wh[k*PAD + 4*l];          // 8B contiguous: cf
        ulonglong2 xx = *(const ulonglong2*)(inq + phys4(k)*4);  // broadcast
        float wj[4];
        h4_to_f4(u, wj);
#pragma unroll
        for (int j = 0; j < 4; ++j) {
            ull w2 = pack2(wj[j], wj[j]);
            z[j][0] = ffma2(w2, xx.x, z[j][0]);
            z[j][1] = ffma2(w2, xx.y, z[j][1]);
        }
    }
}

// Input-layer forward (K=12, fp32 W0), x pairs delivered by warp shuffles.
__device__ __forceinline__ void fwd2x(const float* __restrict__ Wt,
                                      const float* __restrict__ biasg,
                                      ull ua, ull z[4][2], int l)
{
    float4 bb = *(const float4*)&biasg[4*l];
    float bj[4] = {bb.x, bb.y, bb.z, bb.w};
#pragma unroll
    for (int j = 0; j < 4; ++j) {
        ull b2 = pack2(bj[j], bj[j]);
        z[j][0] = b2; z[j][1] = b2;
    }

#pragma unroll
    for (int k = 0; k < NS; ++k) {
        ull x0 = shflx(ua, 2*k);
        ull x1 = shflx(ua, 2*k + 1);
        float4 w4 = *(const float4*)&Wt[k*PAD + 4*l];
        float wj[4] = {w4.x, w4.y, w4.z, w4.w};
#pragma unroll
        for (int j = 0; j < 4; ++j) {
            ull w2 = pack2(wj[j], wj[j]);
            z[j][0] = ffma2(w2, x0, z[j][0]);
            z[j][1] = ffma2(w2, x1, z[j][1]);
        }
    }
}

// Backward vecmat, fp16 weights: r[m][pp] = sum_h g[h][pp] * Wt[(l+32m)][h]
__device__ __forceinline__ void bwd2h(const __half* __restrict__ Wh,
                                      const float* __restrict__ gin,
                                      ull r[4][2], int l)
{
#pragma unroll
    for (int m = 0; m < 4; ++m) { r[m][0] = 0ull; r[m][1] = 0ull; }

#pragma unroll 2
    for (int c = 0; c < 32; ++c) {          // chunks of 4 h-rows
        int perm = (c >> 1) & 3;            // phys4(4c+sg) = 4c + (sg^perm)
        ull g[4][2];
#pragma unroll
        for (int sg = 0; sg < 4; ++sg) {
            ulonglong2 gg = *(const ulonglong2*)(gin + (4*c + (sg ^ perm))*4);
            g[sg][0] = gg.x; g[sg][1] = gg.y;
        }
#pragma unroll
        for (int m = 0; m < 4; ++m) {
            uint2 u = *(const uint2*)&Wh[(l + 32*m)*PAD + 4*c];  // cf (even-bank pairs)
            float wm[4];
            h4_to_f4(u, wm);
#pragma unroll
            for (int sg = 0; sg < 4; ++sg) {
                ull w2 = pack2(wm[sg], wm[sg]);
                r[m][0] = ffma2(w2, g[sg][0], r[m][0]);
                r[m][1] = ffma2(w2, g[sg][1], r[m][1]);
            }
        }
    }
}

__global__ __launch_bounds__(THREADS, 1)
void mlp_kernel(const float* __restrict__ state,
                const float* __restrict__ safe_m, const float* __restrict__ safe_l,
                const float* __restrict__ W0, const float* __restrict__ b0,
                const float* __restrict__ W1, const float* __restrict__ b1,
                const float* __restrict__ W2, const float* __restrict__ b2,
                float* __restrict__ out, int nb)
{
    extern __shared__ float s[];
    __half* W1h = (__half*)(s + OW1H);
    __half* W2h = (__half*)(s + OW2H);
    int tid = threadIdx.x;

    // ---- stage weights into SMEM (transposed, PAD-pitched; W1/W2 as fp16) ----
    for (int i = tid; i < HID*HID; i += THREADS) {
        int h = i >> 7, k = i & 127;
        W1h[k*PAD + h] = __float2half_rn(W1[i]);
        W2h[k*PAD + h] = __float2half_rn(W2[i]);
    }
    for (int i = tid; i < HID*NS; i += THREADS) {
        int h = i / NS, k = i - h*NS;
        s[OW0 + k*PAD + h] = W0[i];
    }
    if (tid < NS) {
        float m = safe_m[tid], lo = safe_l[tid];
        s[OCEN + tid] = 0.5f * (m + lo);
        s[OINV + tid] = 2.0f / (m - lo);
    }
    __syncthreads();

    int w = tid >> 5, l = tid & 31;
    float* BigA = s + OWARP + w*WSTRIDE;     // [128][4] fp32 swizzled: V0->V1->g2->g1->g0
    float* V1h  = BigA + 512;                // [128] 8B fp16 rows, phys16 layout

    int gw = blockIdx.x + GRID * w;          // one task per warp, single wave
    int quads = (nb + NB - 1) / NB;
    if (gw < quads) {
        int base = gw * NB;

        // ---- A: inputs; lane 2k+pp holds pair (x[k][2pp], x[k][2pp+1]) ----
        ull ua;
        {
            int kk = l >> 1; if (kk >= NS) kk -= NS;   // lanes 24..31 duplicate
            int pp = l & 1;
            int i0 = base + 2*pp, i1 = i0 + 1;
            float a0 = (i0 < nb) ? state[i0*NS + kk] : 0.f;
            float a1 = (i1 < nb) ? state[i1*NS + kk] : 0.f;
            float ca = s[OCEN + kk], ia = s[OINV + kk];
            ua = pack2((a0 - ca)*ia, (a1 - ca)*ia);
        }

        ull z[4][2];
        float t[4];

        // ---- B: input layer (K=12, shfl x) + tanh -> V0 (BigA) ----
        fwd2x(s + OW0, b0, ua, z, l);
#pragma unroll
        for (int j = 0; j < 4; ++j) {
            unpack2(z[j][0], t[0], t[1]);
            unpack2(z[j][1], t[2], t[3]);
#pragma unroll
            for (int p = 0; p < 4; ++p) t[p] = ftanh(t[p]);
            store4(BigA, 4*l + j, t);
        }
        __syncwarp();

        // ---- C: layer 1 + tanh -> V1 (in place) + fp16 copy ----
        fwd2h(W1h, b1, BigA, z, l);
        __syncwarp();                        // all V0 reads done before overwrite
#pragma unroll
        for (int j = 0; j < 4; ++j) {
            unpack2(z[j][0], t[0], t[1]);
            unpack2(z[j][1], t[2], t[3]);
#pragma unroll
            for (int p = 0; p < 4; ++p) t[p] = ftanh(t[p]);
            store4(BigA, 4*l + j, t);
            __half2 h0 = __floats2half2_rn(t[0], t[1]);
            __half2 h1 = __floats2half2_rn(t[2], t[3]);
            uint2 u;
            u.x = *(unsigned*)&h0; u.y = *(unsigned*)&h1;
            *(uint2*)&V1h[phys16(4*l + j)*2] = u;
        }
        __syncwarp();

        // ---- D: layer 2 + tanh; vout = R3.V2 (output); g2 -> BigA ----
        fwd2h(W2h, b2, BigA, z, l);
        __syncwarp();                        // V1 reads complete
        {
            ull vo0 = 0ull, vo1 = 0ull;
            float4 r4 = *(const float4*)&g_R3[4*l];
            float rj[4] = {r4.x, r4.y, r4.z, r4.w};
#pragma unroll
            for (int j = 0; j < 4; ++j) {
                ull rj2 = pack2(rj[j], rj[j]);
                unpack2(z[j][0], t[0], t[1]);
                unpack2(z[j][1], t[2], t[3]);
#pragma unroll
                for (int p = 0; p < 4; ++p) t[p] = ftanh(t[p]);
                vo0 = ffma2(rj2, pack2(t[0], t[1]), vo0);
                vo1 = ffma2(rj2, pack2(t[2], t[3]), vo1);
                float gq[4];
#pragma unroll
                for (int p = 0; p < 4; ++p) gq[p] = rj[j] * (1.f - t[p]*t[p]);
                store4(BigA, 4*l + j, gq);
            }
            float vout[4];
            unpack2(vo0, vout[0], vout[1]);
            unpack2(vo1, vout[2], vout[3]);
#pragma unroll
            for (int p = 0; p < 4; ++p) {
                float v = vout[p];
#pragma unroll
                for (int off = 16; off > 0; off >>= 1)
                    v += __shfl_xor_sync(0xffffffffu, v, off);
                vout[p] = v;
            }
            if (l == 0) {
                float c3 = g_c3;
#pragma unroll
                for (int p = 0; p < 4; ++p)
                    if (base + p < nb) out[(base + p)*13] = vout[p] + c3;
            }
        }
        __syncwarp();

        ull r[4][2];

        // ---- E: r = g2.W2 ; s1 from fp16 copy; g1 -> BigA ----
        bwd2h(W2h, BigA, r, l);
        __syncwarp();
#pragma unroll
        for (int m = 0; m < 4; ++m) {
            uint2 u = *(const uint2*)&V1h[phys16(l + 32*m)*2];
            float2 f0 = __half22float2(*(__half2*)&u.x);
            float2 f1 = __half22float2(*(__half2*)&u.y);
            float vp[4] = {f0.x, f0.y, f1.x, f1.y};
            float gq[4];
            float r0, r1;
            unpack2(r[m][0], r0, r1);
            gq[0] = r0 * (1.f - vp[0]*vp[0]);
            gq[1] = r1 * (1.f - vp[1]*vp[1]);
            unpack2(r[m][1], r0, r1);
            gq[2] = r0 * (1.f - vp[2]*vp[2]);
            gq[3] = r1 * (1.f - vp[3]*vp[3]);
            store4(BigA, l + 32*m, gq);
        }
        __syncwarp();

        // ---- F: r = g1.W1 ; then s0 recompute (shfl x) ; g0 -> BigA ----
        bwd2h(W1h, BigA, r, l);
        __syncwarp();                        // all g1 reads done
        {
            ull z0[4][2];
#pragma unroll
            for (int m = 0; m < 4; ++m) {
                float bm = b0[l + 32*m];
                ull b2 = pack2(bm, bm);
                z0[m][0] = b2; z0[m][1] = b2;
            }
#pragma unroll
            for (int k = 0; k < NS; ++k) {
                ull x0 = shflx(ua, 2*k);
                ull x1 = shflx(ua, 2*k + 1);
#pragma unroll
                for (int m = 0; m < 4; ++m) {
                    float wv = s[OW0 + k*PAD + l + 32*m];
                    ull w2 = pack2(wv, wv);
                    z0[m][0] = ffma2(w2, x0, z0[m][0]);
                    z0[m][1] = ffma2(w2, x1, z0[m][1]);
                }
            }
#pragma unroll
            for (int m = 0; m < 4; ++m) {
                float gq[4];
                float a, b, r0, r1;
                unpack2(z0[m][0], a, b);
                a = ftanh(a); b = ftanh(b);
                unpack2(r[m][0], r0, r1);
                gq[0] = r0 * (1.f - a*a);
                gq[1] = r1 * (1.f - b*b);
                unpack2(z0[m][1], a, b);
                a = ftanh(a); b = ftanh(b);
                unpack2(r[m][1], r0, r1);
                gq[2] = r0 * (1.f - a*a);
                gq[3] = r1 * (1.f - b*b);
                store4(BigA, l + 32*m, gq);
            }
        }
        __syncwarp();

        // ---- final: J[k][p] = (sum_h g0[h][p] * W0t[k][h]) * inv[k] ----
        {
            int p  = l & 3;
            int k0 = l >> 2;                 // 0..7
            int k1 = 8 + (k0 & 3);           // 8..11 (lanes >=16 duplicate; store gated)
            float acc0 = 0.f, acc1 = 0.f;
#pragma unroll 2
            for (int i = 0; i < 32; ++i) {   // h = 4i..4i+3
                int perm = (i >> 1) & 3;     // phys4(4i+d) = 4i + (d^perm)
                float4 w0 = *(const float4*)&s[OW0 + k0*PAD + 4*i];
                float4 w1 = *(const float4*)&s[OW0 + k1*PAD + 4*i];
                float gv[4];
#pragma unroll
                for (int d = 0; d < 4; ++d)
                    gv[d] = BigA[(4*i + (d ^ perm))*4 + p];
                acc0 = fmaf(w0.x, gv[0], acc0); acc0 = fmaf(w0.y, gv[1], acc0);
                acc0 = fmaf(w0.z, gv[2], acc0); acc0 = fmaf(w0.w, gv[3], acc0);
                acc1 = fmaf(w1.x, gv[0], acc1); acc1 = fmaf(w1.y, gv[1], acc1);
                acc1 = fmaf(w1.z, gv[2], acc1); acc1 = fmaf(w1.w, gv[3], acc1);
            }
            if (base + p < nb) {
                out[(base + p)*13 + 1 + k0] = acc0 * s[OINV + k0];
                if (l < 16)
                    out[(base + p)*13 + 1 + k1] = acc1 * s[OINV + k1];
            }
        }
    }
}

extern "C" void kernel_launch(void* const* d_in, const int* in_sizes, int n_in,
                              void* d_out, int out_size)
{
    const float* state  = (const float*)d_in[0];
    const float* safe_m = (const float*)d_in[1];
    const float* safe_l = (const float*)d_in[2];
    const float* W0     = (const float*)d_in[3];
    const float* b0     = (const float*)d_in[4];
    const float* W1     = (const float*)d_in[5];
    const float* b1     = (const float*)d_in[6];
    const float* W2     = (const float*)d_in[7];
    const float* b2     = (const float*)d_in[8];
    const float* W3     = (const float*)d_in[9];
    const float* b3     = (const float*)d_in[10];
    const float* Wout   = (const float*)d_in[11];
    const float* bout   = (const float*)d_in[12];
    float* out = (float*)d_out;

    int nb = in_sizes[0] / NS;

    cudaFuncSetAttribute(mlp_kernel, cudaFuncAttributeMaxDynamicSharedMemorySize,
                         SMEM_FLOATS * (int)sizeof(float));

    init_kernel<<<1, HID>>>(W3, b3, Wout, bout);
    mlp_kernel<<<GRID, THREADS, SMEM_FLOATS * sizeof(float)>>>(
        state, safe_m, safe_l, W0, b0, W1, b1, W2, b2, out, nb);
}

// round 10
// speedup vs baseline: 2.2859x; 2.2859x over previous
#include <cuda_runtime.h>
#include <cuda_fp16.h>

#define HID 128
#define NS  12
#define NW  7
#define THREADS (NW*32)
#define GRID 148
#define MROWS 16

typedef unsigned u32;

// ---- SMEM layout (bytes) ----
// W1F 32768 | W1B 32768 | W2F 32768 | W2B 32768 | W0F 4096 | W0B 4096 |
// CONSTS 2304 | STG 65536 (W staging at init; V0save [NW][32][32]u32 at runtime)
#define OFF_W1F 0
#define OFF_W1B 32768
#define OFF_W2F 65536
#define OFF_W2B 98304
#define OFF_W0F 131072
#define OFF_W0B 135168
#define OFF_CON 139264
#define OFF_STG 141568
#define SMEM_BYTES (OFF_STG + 65536)   // 207104

__device__ float g_R3[HID];
__device__ float g_c3;

__global__ void init_kernel(const float* __restrict__ W3, const float* __restrict__ b3,
                            const float* __restrict__ Wout, const float* __restrict__ bout)
{
    int h = threadIdx.x;  // 0..127
    float acc = 0.f;
    for (int j = 0; j < HID; ++j) acc = fmaf(Wout[j], W3[j*HID + h], acc);
    g_R3[h] = acc;
    if (h == 0) {
        float c = bout[0];
        for (int j = 0; j < HID; ++j) c = fmaf(Wout[j], b3[j], c);
        g_c3 = c;
    }
}

__device__ __forceinline__ float ftanh(float x)
{
    float e = __expf(2.0f * x);
    return 1.0f - __fdividef(2.0f, e + 1.0f);
}
__device__ __forceinline__ u32 f2h2(float a, float b)
{
    __half2 h = __floats2half2_rn(a, b);
    return *(u32*)&h;
}
__device__ __forceinline__ float2 h22f2(u32 u)
{
    return __half22float2(*(__half2*)&u);
}
// D = A(16x16) * B(16x8) + D, fp16 in, fp32 accum.
__device__ __forceinline__ void mma16816(float c[4], const u32* a, uint2 b)
{
    asm volatile(
        "mma.sync.aligned.m16n8k16.row.col.f32.f16.f16.f32 "
        "{%0,%1,%2,%3}, {%4,%5,%6,%7}, {%8,%9}, {%0,%1,%2,%3};\n"
        : "+f"(c[0]), "+f"(c[1]), "+f"(c[2]), "+f"(c[3])
        : "r"(a[0]), "r"(a[1]), "r"(a[2]), "r"(a[3]), "r"(b.x), "r"(b.y));
}

__global__ __launch_bounds__(THREADS, 1)
void mlp_kernel(const float* __restrict__ state,
                const float* __restrict__ safe_m, const float* __restrict__ safe_l,
                const float* __restrict__ W0, const float* __restrict__ b0,
                const float* __restrict__ W1, const float* __restrict__ b1,
                const float* __restrict__ W2, const float* __restrict__ b2,
                float* __restrict__ out, int nb)
{
    extern __shared__ char smem[];
    uint2* W1F = (uint2*)(smem + OFF_W1F);
    uint2* W1B = (uint2*)(smem + OFF_W1B);
    uint2* W2F = (uint2*)(smem + OFF_W2F);
    uint2* W2B = (uint2*)(smem + OFF_W2B);
    uint2* W0F = (uint2*)(smem + OFF_W0F);
    uint2* W0B = (uint2*)(smem + OFF_W0B);
    float* CON = (float*)(smem + OFF_CON);
    float* Wraw = (float*)(smem + OFF_STG);

    int tid = threadIdx.x;

    // ---- constants ----
    if (tid < HID) {
        CON[0   + tid] = b0[tid];
        CON[128 + tid] = b1[tid];
        CON[256 + tid] = b2[tid];
        CON[384 + tid] = g_R3[tid];
    }
    if (tid < NS) {
        float m = safe_m[tid], lo = safe_l[tid];
        CON[512 + tid] = 0.5f * (m + lo);
        CON[528 + tid] = 2.0f / (m - lo);
    }
    if (tid == 0) CON[544] = g_c3;

    // ---- build W1 fragments ----
    for (int i = tid; i < HID*HID; i += THREADS) Wraw[i] = W1[i];
    __syncthreads();
    for (int e = tid; e < 128*32; e += THREADS) {
        int T = e >> 5, lf = e & 31;
        int kt = T >> 4, nt = T & 15, qf = lf & 3, gf = lf >> 2;
        int n = 8*nt + gf, k = 16*kt + 2*qf;
        uint2 uf, ub;
        uf.x = f2h2(Wraw[n*HID + k],     Wraw[n*HID + k + 1]);
        uf.y = f2h2(Wraw[n*HID + k + 8], Wraw[n*HID + k + 9]);
        ub.x = f2h2(Wraw[k*HID + n],     Wraw[(k+1)*HID + n]);
        ub.y = f2h2(Wraw[(k+8)*HID + n], Wraw[(k+9)*HID + n]);
        W1F[e] = uf; W1B[e] = ub;
    }
    __syncthreads();
    // ---- W2 ----
    for (int i = tid; i < HID*HID; i += THREADS) Wraw[i] = W2[i];
    __syncthreads();
    for (int e = tid; e < 128*32; e += THREADS) {
        int T = e >> 5, lf = e & 31;
        int kt = T >> 4, nt = T & 15, qf = lf & 3, gf = lf >> 2;
        int n = 8*nt + gf, k = 16*kt + 2*qf;
        uint2 uf, ub;
        uf.x = f2h2(Wraw[n*HID + k],     Wraw[n*HID + k + 1]);
        uf.y = f2h2(Wraw[n*HID + k + 8], Wraw[n*HID + k + 9]);
        ub.x = f2h2(Wraw[k*HID + n],     Wraw[(k+1)*HID + n]);
        ub.y = f2h2(Wraw[(k+8)*HID + n], Wraw[(k+9)*HID + n]);
        W2F[e] = uf; W2B[e] = ub;
    }
    __syncthreads();
    // ---- W0 (128 x 12) ----
    for (int i = tid; i < HID*NS; i += THREADS) Wraw[i] = W0[i];
    __syncthreads();
    for (int e = tid; e < 16*32; e += THREADS) {
        int T = e >> 5, lf = e & 31, qf = lf & 3, gf = lf >> 2;
        {   // W0F: fwd GEMM0, T = nt. B[k][n] = W0[8nt+n][k], k<12 else 0.
            int n = 8*T + gf, k = 2*qf;
            uint2 u;
            u.x = f2h2(Wraw[n*NS + k], Wraw[n*NS + k + 1]);
            u.y = (qf < 2) ? f2h2(Wraw[n*NS + k + 8], Wraw[n*NS + k + 9]) : 0u;
            W0F[e] = u;
        }
        {   // W0B: final J, T: kt=T>>1, nt=T&1. B[k][n] = W0[16kt+k][8nt+n], n<12 else 0.
            int kt = T >> 1, ntb = T & 1;
            int n = 8*ntb + gf, k = 16*kt + 2*qf;
            float w00 = 0.f, w01 = 0.f, w10 = 0.f, w11 = 0.f;
            if (n < NS) {
                w00 = Wraw[k*NS + n];     w01 = Wraw[(k+1)*NS + n];
                w10 = Wraw[(k+8)*NS + n]; w11 = Wraw[(k+9)*NS + n];
            }
            uint2 u; u.x = f2h2(w00, w01); u.y = f2h2(w10, w11);
            W0B[e] = u;
        }
    }
    __syncthreads();
    // staging area now becomes V0save: [NW][32 slots][32 lanes] u32

    int w = tid >> 5, l = tid & 31, q = l & 3, g = l >> 2;
    u32* V0sv = (u32*)Wraw + w*1024 + l;     // V0sv[slot*32]
    const float* B0S = CON;
    const float* B1S = CON + 128;
    const float* B2S = CON + 256;
    const float* R3S = CON + 384;
    const float* CENS = CON + 512;
    const float* INVS = CON + 528;

    int ntask = (nb + MROWS - 1) / MROWS;
    for (int task = blockIdx.x + GRID*w; task < ntask; task += GRID*NW) {
        int base = task * MROWS;
        int ra = base + g, rb = base + g + 8;
        bool oka = ra < nb, okb = rb < nb;

        u32 A0[32], A1[32];

        // ---- X load + normalize -> A0[0..3] (single k-tile) ----
        {
            float2 z2 = make_float2(0.f, 0.f);
            float2 xa = oka ? *(const float2*)&state[ra*NS + 2*q] : z2;
            float2 xb = okb ? *(const float2*)&state[rb*NS + 2*q] : z2;
            float2 xc = z2, xd = z2;
            float c0v = CENS[2*q], c1v = CENS[2*q+1];
            float i0v = INVS[2*q], i1v = INVS[2*q+1];
            xa.x = (xa.x - c0v)*i0v; xa.y = (xa.y - c1v)*i1v;
            xb.x = (xb.x - c0v)*i0v; xb.y = (xb.y - c1v)*i1v;
            if (q < 2) {
                if (oka) xc = *(const float2*)&state[ra*NS + 2*q + 8];
                if (okb) xd = *(const float2*)&state[rb*NS + 2*q + 8];
                float c2v = CENS[2*q+8], c3v = CENS[2*q+9];
                float i2v = INVS[2*q+8], i3v = INVS[2*q+9];
                xc.x = (xc.x - c2v)*i2v; xc.y = (xc.y - c3v)*i3v;
                xd.x = (xd.x - c2v)*i2v; xd.y = (xd.y - c3v)*i3v;
            }
            A0[0] = f2h2(xa.x, xa.y);
            A0[1] = f2h2(xb.x, xb.y);
            A0[2] = f2h2(xc.x, xc.y);
            A0[3] = f2h2(xd.x, xd.y);
        }

        // ---- GEMM0: z0 = X*W0^T + b0 ; V0 = tanh -> A1, save to SMEM ----
#pragma unroll
        for (int nt4 = 0; nt4 < 16; nt4 += 4) {
            float c[4][4];
#pragma unroll
            for (int i = 0; i < 4; ++i) {
                float2 bp = *(const float2*)&B0S[8*(nt4+i) + 2*q];
                c[i][0] = bp.x; c[i][1] = bp.y; c[i][2] = bp.x; c[i][3] = bp.y;
                mma16816(c[i], &A0[0], W0F[(nt4+i)*32 + l]);
            }
#pragma unroll
            for (int i = 0; i < 4; ++i) {
                int nt = nt4 + i, t = nt >> 1, o = (nt & 1) * 2;
                A1[t*4+o]   = f2h2(ftanh(c[i][0]), ftanh(c[i][1]));
                A1[t*4+o+1] = f2h2(ftanh(c[i][2]), ftanh(c[i][3]));
            }
        }
#pragma unroll
        for (int sl = 0; sl < 32; ++sl) V0sv[sl*32] = A1[sl];

        // ---- GEMM1: V1 = tanh(V0*W1^T + b1) -> A0 ----
#pragma unroll
        for (int nt4 = 0; nt4 < 16; nt4 += 4) {
            float c[4][4];
#pragma unroll
            for (int i = 0; i < 4; ++i) {
                float2 bp = *(const float2*)&B1S[8*(nt4+i) + 2*q];
                c[i][0] = bp.x; c[i][1] = bp.y; c[i][2] = bp.x; c[i][3] = bp.y;
            }
#pragma unroll
            for (int kt = 0; kt < 8; ++kt)
#pragma unroll
                for (int i = 0; i < 4; ++i)
                    mma16816(c[i], &A1[kt*4], W1F[(kt*16 + nt4 + i)*32 + l]);
#pragma unroll
            for (int i = 0; i < 4; ++i) {
                int nt = nt4 + i, t = nt >> 1, o = (nt & 1) * 2;
                A0[t*4+o]   = f2h2(ftanh(c[i][0]), ftanh(c[i][1]));
                A0[t*4+o+1] = f2h2(ftanh(c[i][2]), ftanh(c[i][3]));
            }
        }

        // ---- GEMM2: V2 = tanh(V1*W2^T + b2); vout = R3.V2; g2 = R3*(1-V2^2) -> A1 ----
        float vg = 0.f, vg8 = 0.f;
#pragma unroll
        for (int nt4 = 0; nt4 < 16; nt4 += 4) {
            float c[4][4];
#pragma unroll
            for (int i = 0; i < 4; ++i) {
                float2 bp = *(const float2*)&B2S[8*(nt4+i) + 2*q];
                c[i][0] = bp.x; c[i][1] = bp.y; c[i][2] = bp.x; c[i][3] = bp.y;
            }
#pragma unroll
            for (int kt = 0; kt < 8; ++kt)
#pragma unroll
                for (int i = 0; i < 4; ++i)
                    mma16816(c[i], &A0[kt*4], W2F[(kt*16 + nt4 + i)*32 + l]);
#pragma unroll
            for (int i = 0; i < 4; ++i) {
                int nt = nt4 + i, t = nt >> 1, o = (nt & 1) * 2;
                float2 r3p = *(const float2*)&R3S[8*nt + 2*q];
                float t0 = ftanh(c[i][0]), t1 = ftanh(c[i][1]);
                float t2 = ftanh(c[i][2]), t3 = ftanh(c[i][3]);
                vg  += r3p.x*t0 + r3p.y*t1;
                vg8 += r3p.x*t2 + r3p.y*t3;
                A1[t*4+o]   = f2h2(r3p.x*(1.f - t0*t0), r3p.y*(1.f - t1*t1));
                A1[t*4+o+1] = f2h2(r3p.x*(1.f - t2*t2), r3p.y*(1.f - t3*t3));
            }
        }
        vg  += __shfl_xor_sync(0xffffffffu, vg, 1);
        vg  += __shfl_xor_sync(0xffffffffu, vg, 2);
        vg8 += __shfl_xor_sync(0xffffffffu, vg8, 1);
        vg8 += __shfl_xor_sync(0xffffffffu, vg8, 2);
        if (q == 0) {
            float c3 = CON[544];
            if (oka) out[ra*13] = vg + c3;
            if (okb) out[rb*13] = vg8 + c3;
        }

        // ---- B2: r1 = g2*W2 ; g1 = r1*(1-V1^2) -> A0 (in place per nt) ----
#pragma unroll
        for (int nt4 = 0; nt4 < 16; nt4 += 4) {
            float c[4][4];
#pragma unroll
            for (int i = 0; i < 4; ++i) { c[i][0]=0.f; c[i][1]=0.f; c[i][2]=0.f; c[i][3]=0.f; }
#pragma unroll
            for (int kt = 0; kt < 8; ++kt)
#pragma unroll
                for (int i = 0; i < 4; ++i)
                    mma16816(c[i], &A1[kt*4], W2B[(kt*16 + nt4 + i)*32 + l]);
#pragma unroll
            for (int i = 0; i < 4; ++i) {
                int nt = nt4 + i, t = nt >> 1, o = (nt & 1) * 2;
                float2 va = h22f2(A0[t*4+o]);
                float2 vb = h22f2(A0[t*4+o+1]);
                A0[t*4+o]   = f2h2(c[i][0]*(1.f - va.x*va.x), c[i][1]*(1.f - va.y*va.y));
                A0[t*4+o+1] = f2h2(c[i][2]*(1.f - vb.x*vb.x), c[i][3]*(1.f - vb.y*vb.y));
            }
        }

        // ---- B1: r0 = g1*W1 ; g0 = r0*(1-V0^2) -> A1 (V0 from SMEM) ----
#pragma unroll
        for (int nt4 = 0; nt4 < 16; nt4 += 4) {
            float c[4][4];
#pragma unroll
            for (int i = 0; i < 4; ++i) { c[i][0]=0.f; c[i][1]=0.f; c[i][2]=0.f; c[i][3]=0.f; }
#pragma unroll
            for (int kt = 0; kt < 8; ++kt)
#pragma unroll
                for (int i = 0; i < 4; ++i)
                    mma16816(c[i], &A0[kt*4], W1B[(kt*16 + nt4 + i)*32 + l]);
#pragma unroll
            for (int i = 0; i < 4; ++i) {
                int nt = nt4 + i, t = nt >> 1, o = (nt & 1) * 2;
                float2 va = h22f2(V0sv[(t*4+o)*32]);
                float2 vb = h22f2(V0sv[(t*4+o+1)*32]);
                A1[t*4+o]   = f2h2(c[i][0]*(1.f - va.x*va.x), c[i][1]*(1.f - va.y*va.y));
                A1[t*4+o+1] = f2h2(c[i][2]*(1.f - vb.x*vb.x), c[i][3]*(1.f - vb.y*vb.y));
            }
        }

        // ---- J: g0*W0 -> [16x12], scale by inv, store ----
#pragma unroll
        for (int nt = 0; nt < 2; ++nt) {
            float c[4] = {0.f, 0.f, 0.f, 0.f};
#pragma unroll
            for (int kt = 0; kt < 8; ++kt)
                mma16816(c, &A1[kt*4], W0B[(kt*2 + nt)*32 + l]);
            int cb = 8*nt + 2*q;
            if (cb < NS) {
                float iv0 = INVS[cb], iv1 = INVS[cb+1];
                if (oka) {
                    out[ra*13 + 1 + cb]     = c[0]*iv0;
                    out[ra*13 + 1 + cb + 1] = c[1]*iv1;
                }
                if (okb) {
                    out[rb*13 + 1 + cb]     = c[2]*iv0;
                    out[rb*13 + 1 + cb + 1] = c[3]*iv1;
                }
            }
        }
    }
}

extern "C" void kernel_launch(void* const* d_in, const int* in_sizes, int n_in,
                              void* d_out, int out_size)
{
    const float* state  = (const float*)d_in[0];
    const float* safe_m = (const float*)d_in[1];
    const float* safe_l = (const float*)d_in[2];
    const float* W0     = (const float*)d_in[3];
    const float* b0     = (const float*)d_in[4];
    const float* W1     = (const float*)d_in[5];
    const float* b1     = (const float*)d_in[6];
    const float* W2     = (const float*)d_in[7];
    const float* b2     = (const float*)d_in[8];
    const float* W3     = (const float*)d_in[9];
    const float* b3     = (const float*)d_in[10];
    const float* Wout   = (const float*)d_in[11];
    const float* bout   = (const float*)d_in[12];
    float* out = (float*)d_out;

    int nb = in_sizes[0] / NS;

    cudaFuncSetAttribute(mlp_kernel, cudaFuncAttributeMaxDynamicSharedMemorySize,
                         SMEM_BYTES);

    init_kernel<<<1, HID>>>(W3, b3, Wout, bout);
    mlp_kernel<<<GRID, THREADS, SMEM_BYTES>>>(
        state, safe_m, safe_l, W0, b0, W1, b1, W2, b2, out, nb);
}

// round 11
// speedup vs baseline: 2.4777x; 1.0839x over previous
#include <cuda_runtime.h>
#include <cuda_fp16.h>

#define HID 128
#define NS  12
#define NW  14
#define PAIRS (NW/2)
#define THREADS (NW*32)
#define GRID 148
#define MROWS 16

typedef unsigned u32;

// ---- SMEM layout (bytes) ----
#define OFF_W1F 0
#define OFF_W1B 32768
#define OFF_W2F 65536
#define OFF_W2B 98304
#define OFF_W0F 131072
#define OFF_W0B 135168
#define OFF_CON 139264
#define OFF_STG 141568
#define PBSTRIDE 12352               // ACT 4096 | V0s 4096 | V1s 4096 | VX 64
#define SMEM_BYTES (OFF_STG + PAIRS*PBSTRIDE)   // 228032

__device__ float g_R3[HID];
__device__ float g_c3;

__global__ void init_kernel(const float* __restrict__ W3, const float* __restrict__ b3,
                            const float* __restrict__ Wout, const float* __restrict__ bout)
{
    int h = threadIdx.x;  // 0..127
    float acc = 0.f;
    for (int j = 0; j < HID; ++j) acc = fmaf(Wout[j], W3[j*HID + h], acc);
    g_R3[h] = acc;
    if (h == 0) {
        float c = bout[0];
        for (int j = 0; j < HID; ++j) c = fmaf(Wout[j], b3[j], c);
        g_c3 = c;
    }
}

__device__ __forceinline__ float ftanh(float x)
{
    float e = __expf(2.0f * x);
    return 1.0f - __fdividef(2.0f, e + 1.0f);
}
__device__ __forceinline__ u32 f2h2(float a, float b)
{
    __half2 h = __floats2half2_rn(a, b);
    return *(u32*)&h;
}
__device__ __forceinline__ float2 h22f2(u32 u)
{
    return __half22float2(*(__half2*)&u);
}
__device__ __forceinline__ void mma16816(float c[4], const u32* a, uint2 b)
{
    asm volatile(
        "mma.sync.aligned.m16n8k16.row.col.f32.f16.f16.f32 "
        "{%0,%1,%2,%3}, {%4,%5,%6,%7}, {%8,%9}, {%0,%1,%2,%3};\n"
        : "+f"(c[0]), "+f"(c[1]), "+f"(c[2]), "+f"(c[3])
        : "r"(a[0]), "r"(a[1]), "r"(a[2]), "r"(a[3]), "r"(b.x), "r"(b.y));
}
__device__ __forceinline__ void bar_pair(int id)
{
    asm volatile("bar.sync %0, 64;" :: "r"(id) : "memory");
}

__global__ __launch_bounds__(THREADS, 1)
void mlp_kernel(const float* __restrict__ state,
                const float* __restrict__ safe_m, const float* __restrict__ safe_l,
                const float* __restrict__ W0, const float* __restrict__ b0,
                const float* __restrict__ W1, const float* __restrict__ b1,
                const float* __restrict__ W2, const float* __restrict__ b2,
                float* __restrict__ out, int nb)
{
    extern __shared__ char smem[];
    uint2* W1F = (uint2*)(smem + OFF_W1F);
    uint2* W1B = (uint2*)(smem + OFF_W1B);
    uint2* W2F = (uint2*)(smem + OFF_W2F);
    uint2* W2B = (uint2*)(smem + OFF_W2B);
    uint2* W0F = (uint2*)(smem + OFF_W0F);
    uint2* W0B = (uint2*)(smem + OFF_W0B);
    float* CON = (float*)(smem + OFF_CON);
    float* Wraw = (float*)(smem + OFF_STG);

    int tid = threadIdx.x;

    // ---- constants ----
    if (tid < HID) {
        CON[0   + tid] = b0[tid];
        CON[128 + tid] = b1[tid];
        CON[256 + tid] = b2[tid];
        CON[384 + tid] = g_R3[tid];
    }
    if (tid < NS) {
        float m = safe_m[tid], lo = safe_l[tid];
        CON[512 + tid] = 0.5f * (m + lo);
        CON[528 + tid] = 2.0f / (m - lo);
    }
    if (tid == 0) CON[544] = g_c3;

    // ---- build W1 fragments ----
    for (int i = tid; i < HID*HID; i += THREADS) Wraw[i] = W1[i];
    __syncthreads();
    for (int e = tid; e < 128*32; e += THREADS) {
        int T = e >> 5, lf = e & 31;
        int kt = T >> 4, nt = T & 15, qf = lf & 3, gf = lf >> 2;
        int n = 8*nt + gf, k = 16*kt + 2*qf;
        uint2 uf, ub;
        uf.x = f2h2(Wraw[n*HID + k],     Wraw[n*HID + k + 1]);
        uf.y = f2h2(Wraw[n*HID + k + 8], Wraw[n*HID + k + 9]);
        ub.x = f2h2(Wraw[k*HID + n],     Wraw[(k+1)*HID + n]);
        ub.y = f2h2(Wraw[(k+8)*HID + n], Wraw[(k+9)*HID + n]);
        W1F[e] = uf; W1B[e] = ub;
    }
    __syncthreads();
    // ---- W2 ----
    for (int i = tid; i < HID*HID; i += THREADS) Wraw[i] = W2[i];
    __syncthreads();
    for (int e = tid; e < 128*32; e += THREADS) {
        int T = e >> 5, lf = e & 31;
        int kt = T >> 4, nt = T & 15, qf = lf & 3, gf = lf >> 2;
        int n = 8*nt + gf, k = 16*kt + 2*qf;
        uint2 uf, ub;
        uf.x = f2h2(Wraw[n*HID + k],     Wraw[n*HID + k + 1]);
        uf.y = f2h2(Wraw[n*HID + k + 8], Wraw[n*HID + k + 9]);
        ub.x = f2h2(Wraw[k*HID + n],     Wraw[(k+1)*HID + n]);
        ub.y = f2h2(Wraw[(k+8)*HID + n], Wraw[(k+9)*HID + n]);
        W2F[e] = uf; W2B[e] = ub;
    }
    __syncthreads();
    // ---- W0 (128 x 12) ----
    for (int i = tid; i < HID*NS; i += THREADS) Wraw[i] = W0[i];
    __syncthreads();
    for (int e = tid; e < 16*32; e += THREADS) {
        int T = e >> 5, lf = e & 31, qf = lf & 3, gf = lf >> 2;
        {   // W0F: fwd GEMM0, T = nt
            int n = 8*T + gf, k = 2*qf;
            uint2 u;
            u.x = f2h2(Wraw[n*NS + k], Wraw[n*NS + k + 1]);
            u.y = (qf < 2) ? f2h2(Wraw[n*NS + k + 8], Wraw[n*NS + k + 9]) : 0u;
            W0F[e] = u;
        }
        {   // W0B: final J, kt=T>>1, nt=T&1
            int kt = T >> 1, ntb = T & 1;
            int n = 8*ntb + gf, k = 16*kt + 2*qf;
            float w00 = 0.f, w01 = 0.f, w10 = 0.f, w11 = 0.f;
            if (n < NS) {
                w00 = Wraw[k*NS + n];     w01 = Wraw[(k+1)*NS + n];
                w10 = Wraw[(k+8)*NS + n]; w11 = Wraw[(k+9)*NS + n];
            }
            uint2 u; u.x = f2h2(w00, w01); u.y = f2h2(w10, w11);
            W0B[e] = u;
        }
    }
    __syncthreads();
    // staging region becomes per-pair buffers

    int w = tid >> 5, l = tid & 31, q = l & 3, g = l >> 2;
    int pair = w >> 1, wa = w & 1;
    char* PB = smem + OFF_STG + pair*PBSTRIDE;
    uint2* ACT = (uint2*)PB;              // [16 nt][32 lanes] activation exchange
    uint2* V0s = (uint2*)(PB + 4096);
    uint2* V1s = (uint2*)(PB + 8192);
    float* VX  = (float*)(PB + 12288);    // 16 floats vout exchange
    int barid = pair + 1;

    const float* B0S = CON;
    const float* B1S = CON + 128;
    const float* B2S = CON + 256;
    const float* R3S = CON + 384;
    const float* CENS = CON + 512;
    const float* INVS = CON + 528;

    int nt0 = 8*wa;                       // this warp's n-tile half

    int ntask = (nb + MROWS - 1) / MROWS;
    for (int task = blockIdx.x + GRID*pair; task < ntask; task += GRID*PAIRS) {
        int base = task * MROWS;
        int ra = base + g, rb = base + g + 8;
        bool oka = ra < nb, okb = rb < nb;

        u32 A[32];

        // ---- X load + normalize -> A[0..3] ----
        {
            float2 z2 = make_float2(0.f, 0.f);
            float2 xa = oka ? *(const float2*)&state[ra*NS + 2*q] : z2;
            float2 xb = okb ? *(const float2*)&state[rb*NS + 2*q] : z2;
            float2 xc = z2, xd = z2;
            float c0v = CENS[2*q], c1v = CENS[2*q+1];
            float i0v = INVS[2*q], i1v = INVS[2*q+1];
            xa.x = (xa.x - c0v)*i0v; xa.y = (xa.y - c1v)*i1v;
            xb.x = (xb.x - c0v)*i0v; xb.y = (xb.y - c1v)*i1v;
            if (q < 2) {
                if (oka) xc = *(const float2*)&state[ra*NS + 2*q + 8];
                if (okb) xd = *(const float2*)&state[rb*NS + 2*q + 8];
                float c2v = CENS[2*q+8], c3v = CENS[2*q+9];
                float i2v = INVS[2*q+8], i3v = INVS[2*q+9];
                xc.x = (xc.x - c2v)*i2v; xc.y = (xc.y - c3v)*i3v;
                xd.x = (xd.x - c2v)*i2v; xd.y = (xd.y - c3v)*i3v;
            }
            A[0] = f2h2(xa.x, xa.y);
            A[1] = f2h2(xb.x, xb.y);
            A[2] = f2h2(xc.x, xc.y);
            A[3] = f2h2(xd.x, xd.y);
        }

        // ---- GEMM0: V0 = tanh(X*W0^T + b0) for nt half -> ACT, V0s ----
#pragma unroll
        for (int i4 = 0; i4 < 8; i4 += 4) {
            float c[4][4];
#pragma unroll
            for (int i = 0; i < 4; ++i) {
                int nt = nt0 + i4 + i;
                float2 bp = *(const float2*)&B0S[8*nt + 2*q];
                c[i][0] = bp.x; c[i][1] = bp.y; c[i][2] = bp.x; c[i][3] = bp.y;
                mma16816(c[i], &A[0], W0F[nt*32 + l]);
            }
#pragma unroll
            for (int i = 0; i < 4; ++i) {
                int nt = nt0 + i4 + i;
                uint2 u;
                u.x = f2h2(ftanh(c[i][0]), ftanh(c[i][1]));
                u.y = f2h2(ftanh(c[i][2]), ftanh(c[i][3]));
                ACT[nt*32 + l] = u;
                V0s[nt*32 + l] = u;
            }
        }
        bar_pair(barid);                         // GEMM0 writes visible

        // ---- GEMM1: V1 = tanh(V0*W1^T + b1) -> ACT, V1s ----
#pragma unroll
        for (int j = 0; j < 16; ++j) {
            uint2 v = ACT[j*32 + l];
            A[2*j] = v.x; A[2*j+1] = v.y;
        }
        bar_pair(barid);                         // reads done before overwrite
#pragma unroll
        for (int i4 = 0; i4 < 8; i4 += 4) {
            float c[4][4];
#pragma unroll
            for (int i = 0; i < 4; ++i) {
                int nt = nt0 + i4 + i;
                float2 bp = *(const float2*)&B1S[8*nt + 2*q];
                c[i][0] = bp.x; c[i][1] = bp.y; c[i][2] = bp.x; c[i][3] = bp.y;
            }
#pragma unroll
            for (int kt = 0; kt < 8; ++kt)
#pragma unroll
                for (int i = 0; i < 4; ++i)
                    mma16816(c[i], &A[kt*4], W1F[(kt*16 + nt0 + i4 + i)*32 + l]);
#pragma unroll
            for (int i = 0; i < 4; ++i) {
                int nt = nt0 + i4 + i;
                uint2 u;
                u.x = f2h2(ftanh(c[i][0]), ftanh(c[i][1]));
                u.y = f2h2(ftanh(c[i][2]), ftanh(c[i][3]));
                ACT[nt*32 + l] = u;
                V1s[nt*32 + l] = u;
            }
        }
        bar_pair(barid);

        // ---- GEMM2: V2 = tanh(V1*W2^T + b2); vout partial; g2 -> ACT ----
#pragma unroll
        for (int j = 0; j < 16; ++j) {
            uint2 v = ACT[j*32 + l];
            A[2*j] = v.x; A[2*j+1] = v.y;
        }
        bar_pair(barid);
        float vg = 0.f, vg8 = 0.f;
#pragma unroll
        for (int i4 = 0; i4 < 8; i4 += 4) {
            float c[4][4];
#pragma unroll
            for (int i = 0; i < 4; ++i) {
                int nt = nt0 + i4 + i;
                float2 bp = *(const float2*)&B2S[8*nt + 2*q];
                c[i][0] = bp.x; c[i][1] = bp.y; c[i][2] = bp.x; c[i][3] = bp.y;
            }
#pragma unroll
            for (int kt = 0; kt < 8; ++kt)
#pragma unroll
                for (int i = 0; i < 4; ++i)
                    mma16816(c[i], &A[kt*4], W2F[(kt*16 + nt0 + i4 + i)*32 + l]);
#pragma unroll
            for (int i = 0; i < 4; ++i) {
                int nt = nt0 + i4 + i;
                float2 r3p = *(const float2*)&R3S[8*nt + 2*q];
                float t0 = ftanh(c[i][0]), t1 = ftanh(c[i][1]);
                float t2 = ftanh(c[i][2]), t3 = ftanh(c[i][3]);
                vg  += r3p.x*t0 + r3p.y*t1;
                vg8 += r3p.x*t2 + r3p.y*t3;
                uint2 u;
                u.x = f2h2(r3p.x*(1.f - t0*t0), r3p.y*(1.f - t1*t1));
                u.y = f2h2(r3p.x*(1.f - t2*t2), r3p.y*(1.f - t3*t3));
                ACT[nt*32 + l] = u;
            }
        }
        vg  += __shfl_xor_sync(0xffffffffu, vg, 1);
        vg  += __shfl_xor_sync(0xffffffffu, vg, 2);
        vg8 += __shfl_xor_sync(0xffffffffu, vg8, 1);
        vg8 += __shfl_xor_sync(0xffffffffu, vg8, 2);
        if (wa == 1 && q == 0) { VX[g] = vg; VX[8+g] = vg8; }
        bar_pair(barid);                         // g2 + VX visible
        if (wa == 0 && q == 0) {
            float c3 = CON[544];
            if (oka) out[ra*13] = vg + VX[g] + c3;
            if (okb) out[rb*13] = vg8 + VX[8+g] + c3;
        }

        // ---- B2: r1 = g2*W2 ; g1 = r1*(1-V1^2) -> ACT ----
#pragma unroll
        for (int j = 0; j < 16; ++j) {
            uint2 v = ACT[j*32 + l];
            A[2*j] = v.x; A[2*j+1] = v.y;
        }
        bar_pair(barid);
#pragma unroll
        for (int i4 = 0; i4 < 8; i4 += 4) {
            float c[4][4];
#pragma unroll
            for (int i = 0; i < 4; ++i) { c[i][0]=0.f; c[i][1]=0.f; c[i][2]=0.f; c[i][3]=0.f; }
#pragma unroll
            for (int kt = 0; kt < 8; ++kt)
#pragma unroll
                for (int i = 0; i < 4; ++i)
                    mma16816(c[i], &A[kt*4], W2B[(kt*16 + nt0 + i4 + i)*32 + l]);
#pragma unroll
            for (int i = 0; i < 4; ++i) {
                int nt = nt0 + i4 + i;
                uint2 v1 = V1s[nt*32 + l];
                float2 va = h22f2(v1.x), vb = h22f2(v1.y);
                uint2 u;
                u.x = f2h2(c[i][0]*(1.f - va.x*va.x), c[i][1]*(1.f - va.y*va.y));
                u.y = f2h2(c[i][2]*(1.f - vb.x*vb.x), c[i][3]*(1.f - vb.y*vb.y));
                ACT[nt*32 + l] = u;
            }
        }
        bar_pair(barid);

        // ---- B1: r0 = g1*W1 ; g0 = r0*(1-V0^2) -> ACT ----
#pragma unroll
        for (int j = 0; j < 16; ++j) {
            uint2 v = ACT[j*32 + l];
            A[2*j] = v.x; A[2*j+1] = v.y;
        }
        bar_pair(barid);
#pragma unroll
        for (int i4 = 0; i4 < 8; i4 += 4) {
            float c[4][4];
#pragma unroll
            for (int i = 0; i < 4; ++i) { c[i][0]=0.f; c[i][1]=0.f; c[i][2]=0.f; c[i][3]=0.f; }
#pragma unroll
            for (int kt = 0; kt < 8; ++kt)
#pragma unroll
                for (int i = 0; i < 4; ++i)
                    mma16816(c[i], &A[kt*4], W1B[(kt*16 + nt0 + i4 + i)*32 + l]);
#pragma unroll
            for (int i = 0; i < 4; ++i) {
                int nt = nt0 + i4 + i;
                uint2 v0 = V0s[nt*32 + l];
                float2 va = h22f2(v0.x), vb = h22f2(v0.y);
                uint2 u;
                u.x = f2h2(c[i][0]*(1.f - va.x*va.x), c[i][1]*(1.f - va.y*va.y));
                u.y = f2h2(c[i][2]*(1.f - vb.x*vb.x), c[i][3]*(1.f - vb.y*vb.y));
                ACT[nt*32 + l] = u;
            }
        }
        bar_pair(barid);

        // ---- J: g0*W0 -> [16x12]; warp wa does n-tile wa ----
#pragma unroll
        for (int j = 0; j < 16; ++j) {
            uint2 v = ACT[j*32 + l];
            A[2*j] = v.x; A[2*j+1] = v.y;
        }
        bar_pair(barid);                         // reads done; next iter may overwrite
        {
            float c[4] = {0.f, 0.f, 0.f, 0.f};
#pragma unroll
            for (int kt = 0; kt < 8; ++kt)
                mma16816(c, &A[kt*4], W0B[(kt*2 + wa)*32 + l]);
            int cb = 8*wa + 2*q;
            if (cb < NS) {
                float iv0 = INVS[cb], iv1 = INVS[cb+1];
                if (oka) {
                    out[ra*13 + 1 + cb]     = c[0]*iv0;
                    out[ra*13 + 1 + cb + 1] = c[1]*iv1;
                }
                if (okb) {
                    out[rb*13 + 1 + cb]     = c[2]*iv0;
                    out[rb*13 + 1 + cb + 1] = c[3]*iv1;
                }
            }
        }
    }
}

extern "C" void kernel_launch(void* const* d_in, const int* in_sizes, int n_in,
                              void* d_out, int out_size)
{
    const float* state  = (const float*)d_in[0];
    const float* safe_m = (const float*)d_in[1];
    const float* safe_l = (const float*)d_in[2];
    const float* W0     = (const float*)d_in[3];
    const float* b0     = (const float*)d_in[4];
    const float* W1     = (const float*)d_in[5];
    const float* b1     = (const float*)d_in[6];
    const float* W2     = (const float*)d_in[7];
    const float* b2     = (const float*)d_in[8];
    const float* W3     = (const float*)d_in[9];
    const float* b3     = (const float*)d_in[10];
    const float* Wout   = (const float*)d_in[11];
    const float* bout   = (const float*)d_in[12];
    float* out = (float*)d_out;

    int nb = in_sizes[0] / NS;

    cudaFuncSetAttribute(mlp_kernel, cudaFuncAttributeMaxDynamicSharedMemorySize,
                         SMEM_BYTES);

    init_kernel<<<1, HID>>>(W3, b3, Wout, bout);
    mlp_kernel<<<GRID, THREADS, SMEM_BYTES>>>(
        state, safe_m, safe_l, W0, b0, W1, b1, W2, b2, out, nb);
}

// round 12
// speedup vs baseline: 2.7932x; 1.1273x over previous
#include <cuda_runtime.h>
#include <cuda_fp16.h>

#define HID 128
#define NS  12
#define NW  14
#define PAIRS (NW/2)
#define THREADS (NW*32)
#define GRID 148
#define MROWS 16

typedef unsigned u32;

// ---- SMEM layout (bytes) ----
#define OFF_W1F 0
#define OFF_W1B 32768
#define OFF_W2F 65536
#define OFF_W2B 98304
#define OFF_W0F 131072
#define OFF_W0B 135168
#define OFF_CON 139264
#define OFF_PB  141568
#define PBSTRIDE 8256                // ACTa 4096 | ACTb 4096 | VX 64
#define SMEM_BYTES (OFF_PB + PAIRS*PBSTRIDE)   // 199360

__device__ float g_R3[HID];
__device__ float g_c3;

__global__ void init_kernel(const float* __restrict__ W3, const float* __restrict__ b3,
                            const float* __restrict__ Wout, const float* __restrict__ bout)
{
    int h = threadIdx.x;  // 0..127
    float acc = 0.f;
    for (int j = 0; j < HID; ++j) acc = fmaf(Wout[j], W3[j*HID + h], acc);
    g_R3[h] = acc;
    if (h == 0) {
        float c = bout[0];
        for (int j = 0; j < HID; ++j) c = fmaf(Wout[j], b3[j], c);
        g_c3 = c;
    }
}

__device__ __forceinline__ float ftanh(float x)
{
    float e = __expf(2.0f * x);
    return 1.0f - __fdividef(2.0f, e + 1.0f);
}
__device__ __forceinline__ u32 f2h2(float a, float b)
{
    __half2 h = __floats2half2_rn(a, b);
    return *(u32*)&h;
}
__device__ __forceinline__ float2 h22f2(u32 u)
{
    return __half22float2(*(__half2*)&u);
}
__device__ __forceinline__ void mma16816(float c[4], const u32* a, uint2 b)
{
    asm volatile(
        "mma.sync.aligned.m16n8k16.row.col.f32.f16.f16.f32 "
        "{%0,%1,%2,%3}, {%4,%5,%6,%7}, {%8,%9}, {%0,%1,%2,%3};\n"
        : "+f"(c[0]), "+f"(c[1]), "+f"(c[2]), "+f"(c[3])
        : "r"(a[0]), "r"(a[1]), "r"(a[2]), "r"(a[3]), "r"(b.x), "r"(b.y));
}
__device__ __forceinline__ void bar_pair(int id)
{
    asm volatile("bar.sync %0, 64;" :: "r"(id) : "memory");
}

__global__ __launch_bounds__(THREADS, 1)
void mlp_kernel(const float* __restrict__ state,
                const float* __restrict__ safe_m, const float* __restrict__ safe_l,
                const float* __restrict__ W0, const float* __restrict__ b0,
                const float* __restrict__ W1, const float* __restrict__ b1,
                const float* __restrict__ W2, const float* __restrict__ b2,
                float* __restrict__ out, int nb)
{
    extern __shared__ char smem[];
    uint2* W1F = (uint2*)(smem + OFF_W1F);
    uint2* W1B = (uint2*)(smem + OFF_W1B);
    uint2* W2F = (uint2*)(smem + OFF_W2F);
    uint2* W2B = (uint2*)(smem + OFF_W2B);
    uint2* W0F = (uint2*)(smem + OFF_W0F);
    uint2* W0B = (uint2*)(smem + OFF_W0B);
    float* CON = (float*)(smem + OFF_CON);

    int tid = threadIdx.x;

    // ---- constants ----
    if (tid < HID) {
        CON[0   + tid] = b0[tid];
        CON[128 + tid] = b1[tid];
        CON[256 + tid] = b2[tid];
        CON[384 + tid] = g_R3[tid];
    }
    if (tid < NS) {
        float m = safe_m[tid], lo = safe_l[tid];
        CON[512 + tid] = 0.5f * (m + lo);
        CON[528 + tid] = 2.0f / (m - lo);
    }
    if (tid == 0) CON[544] = g_c3;

    // ---- build W1/W2 fragments directly from global (L2-broadcast) ----
    for (int e = tid; e < 128*32; e += THREADS) {
        int T = e >> 5, lf = e & 31;
        int kt = T >> 4, nt = T & 15, qf = lf & 3, gf = lf >> 2;
        int n = 8*nt + gf, k = 16*kt + 2*qf;
        {
            float2 wlo = *(const float2*)&W1[n*HID + k];
            float2 whi = *(const float2*)&W1[n*HID + k + 8];
            uint2 uf; uf.x = f2h2(wlo.x, wlo.y); uf.y = f2h2(whi.x, whi.y);
            uint2 ub;
            ub.x = f2h2(W1[k*HID + n],     W1[(k+1)*HID + n]);
            ub.y = f2h2(W1[(k+8)*HID + n], W1[(k+9)*HID + n]);
            W1F[e] = uf; W1B[e] = ub;
        }
        {
            float2 wlo = *(const float2*)&W2[n*HID + k];
            float2 whi = *(const float2*)&W2[n*HID + k + 8];
            uint2 uf; uf.x = f2h2(wlo.x, wlo.y); uf.y = f2h2(whi.x, whi.y);
            uint2 ub;
            ub.x = f2h2(W2[k*HID + n],     W2[(k+1)*HID + n]);
            ub.y = f2h2(W2[(k+8)*HID + n], W2[(k+9)*HID + n]);
            W2F[e] = uf; W2B[e] = ub;
        }
    }
    for (int e = tid; e < 16*32; e += THREADS) {
        int T = e >> 5, lf = e & 31, qf = lf & 3, gf = lf >> 2;
        {   // W0F: fwd GEMM0, T = nt
            int n = 8*T + gf, k = 2*qf;
            uint2 u;
            u.x = f2h2(W0[n*NS + k], W0[n*NS + k + 1]);
            u.y = (qf < 2) ? f2h2(W0[n*NS + k + 8], W0[n*NS + k + 9]) : 0u;
            W0F[e] = u;
        }
        {   // W0B: final J, kt=T>>1, nt=T&1
            int kt = T >> 1, ntb = T & 1;
            int n = 8*ntb + gf, k = 16*kt + 2*qf;
            float w00 = 0.f, w01 = 0.f, w10 = 0.f, w11 = 0.f;
            if (n < NS) {
                w00 = W0[k*NS + n];     w01 = W0[(k+1)*NS + n];
                w10 = W0[(k+8)*NS + n]; w11 = W0[(k+9)*NS + n];
            }
            uint2 u; u.x = f2h2(w00, w01); u.y = f2h2(w10, w11);
            W0B[e] = u;
        }
    }
    __syncthreads();

    int w = tid >> 5, l = tid & 31, q = l & 3, g = l >> 2;
    int pair = w >> 1, wa = w & 1;
    char* PB = smem + OFF_PB + pair*PBSTRIDE;
    uint2* ACTa = (uint2*)PB;             // [16 nt][32 lanes]
    uint2* ACTb = (uint2*)(PB + 4096);
    float* VX   = (float*)(PB + 8192);
    int barid = pair + 1;

    const float* B0S = CON;
    const float* B1S = CON + 128;
    const float* B2S = CON + 256;
    const float* R3S = CON + 384;
    const float* CENS = CON + 512;
    const float* INVS = CON + 528;

    int nt0 = 8*wa;                       // this warp's n-tile half

    int ntask = (nb + MROWS - 1) / MROWS;
    for (int task = blockIdx.x + GRID*pair; task < ntask; task += GRID*PAIRS) {
        int base = task * MROWS;
        int ra = base + g, rb = base + g + 8;
        bool oka = ra < nb, okb = rb < nb;

        u32 A[32];
        u32 V0k[16], V1k[16];             // own-half V0/V1 (fp16 pairs), register-resident
        float c[8][4];

        // ---- X load + normalize -> A[0..3] ----
        {
            float2 z2 = make_float2(0.f, 0.f);
            float2 xa = oka ? *(const float2*)&state[ra*NS + 2*q] : z2;
            float2 xb = okb ? *(const float2*)&state[rb*NS + 2*q] : z2;
            float2 xc = z2, xd = z2;
            float c0v = CENS[2*q], c1v = CENS[2*q+1];
            float i0v = INVS[2*q], i1v = INVS[2*q+1];
            xa.x = (xa.x - c0v)*i0v; xa.y = (xa.y - c1v)*i1v;
            xb.x = (xb.x - c0v)*i0v; xb.y = (xb.y - c1v)*i1v;
            if (q < 2) {
                if (oka) xc = *(const float2*)&state[ra*NS + 2*q + 8];
                if (okb) xd = *(const float2*)&state[rb*NS + 2*q + 8];
                float c2v = CENS[2*q+8], c3v = CENS[2*q+9];
                float i2v = INVS[2*q+8], i3v = INVS[2*q+9];
                xc.x = (xc.x - c2v)*i2v; xc.y = (xc.y - c3v)*i3v;
                xd.x = (xd.x - c2v)*i2v; xd.y = (xd.y - c3v)*i3v;
            }
            A[0] = f2h2(xa.x, xa.y);
            A[1] = f2h2(xb.x, xb.y);
            A[2] = f2h2(xc.x, xc.y);
            A[3] = f2h2(xd.x, xd.y);
        }

        // ---- G0: V0 = tanh(X*W0^T + b0) -> ACTa + V0k ----
#pragma unroll
        for (int i = 0; i < 8; ++i) {
            int nt = nt0 + i;
            float2 bp = *(const float2*)&B0S[8*nt + 2*q];
            c[i][0] = bp.x; c[i][1] = bp.y; c[i][2] = bp.x; c[i][3] = bp.y;
            mma16816(c[i], &A[0], W0F[nt*32 + l]);
        }
#pragma unroll
        for (int i = 0; i < 8; ++i) {
            uint2 u;
            u.x = f2h2(ftanh(c[i][0]), ftanh(c[i][1]));
            u.y = f2h2(ftanh(c[i][2]), ftanh(c[i][3]));
            ACTa[(nt0 + i)*32 + l] = u;
            V0k[2*i] = u.x; V0k[2*i+1] = u.y;
        }
        bar_pair(barid);                             // (1) ACTa complete

        // ---- G1: V1 = tanh(V0*W1^T + b1): read a -> write b + V1k ----
#pragma unroll
        for (int j = 0; j < 16; ++j) {
            uint2 v = ACTa[j*32 + l];
            A[2*j] = v.x; A[2*j+1] = v.y;
        }
#pragma unroll
        for (int i = 0; i < 8; ++i) {
            float2 bp = *(const float2*)&B1S[8*(nt0+i) + 2*q];
            c[i][0] = bp.x; c[i][1] = bp.y; c[i][2] = bp.x; c[i][3] = bp.y;
        }
#pragma unroll
        for (int kt = 0; kt < 8; ++kt)
#pragma unroll
            for (int i = 0; i < 8; ++i)
                mma16816(c[i], &A[kt*4], W1F[(kt*16 + nt0 + i)*32 + l]);
#pragma unroll
        for (int i = 0; i < 8; ++i) {
            uint2 u;
            u.x = f2h2(ftanh(c[i][0]), ftanh(c[i][1]));
            u.y = f2h2(ftanh(c[i][2]), ftanh(c[i][3]));
            ACTb[(nt0 + i)*32 + l] = u;
            V1k[2*i] = u.x; V1k[2*i+1] = u.y;
        }
        bar_pair(barid);                             // (2) ACTb complete

        // ---- G2: V2 = tanh(V1*W2^T + b2); vout partial; g2: read b -> write a ----
#pragma unroll
        for (int j = 0; j < 16; ++j) {
            uint2 v = ACTb[j*32 + l];
            A[2*j] = v.x; A[2*j+1] = v.y;
        }
#pragma unroll
        for (int i = 0; i < 8; ++i) {
            float2 bp = *(const float2*)&B2S[8*(nt0+i) + 2*q];
            c[i][0] = bp.x; c[i][1] = bp.y; c[i][2] = bp.x; c[i][3] = bp.y;
        }
#pragma unroll
        for (int kt = 0; kt < 8; ++kt)
#pragma unroll
            for (int i = 0; i < 8; ++i)
                mma16816(c[i], &A[kt*4], W2F[(kt*16 + nt0 + i)*32 + l]);
        float vg = 0.f, vg8 = 0.f;
#pragma unroll
        for (int i = 0; i < 8; ++i) {
            int nt = nt0 + i;
            float2 r3p = *(const float2*)&R3S[8*nt + 2*q];
            float t0 = ftanh(c[i][0]), t1 = ftanh(c[i][1]);
            float t2 = ftanh(c[i][2]), t3 = ftanh(c[i][3]);
            vg  += r3p.x*t0 + r3p.y*t1;
            vg8 += r3p.x*t2 + r3p.y*t3;
            uint2 u;
            u.x = f2h2(r3p.x*(1.f - t0*t0), r3p.y*(1.f - t1*t1));
            u.y = f2h2(r3p.x*(1.f - t2*t2), r3p.y*(1.f - t3*t3));
            ACTa[nt*32 + l] = u;
        }
        vg  += __shfl_xor_sync(0xffffffffu, vg, 1);
        vg  += __shfl_xor_sync(0xffffffffu, vg, 2);
        vg8 += __shfl_xor_sync(0xffffffffu, vg8, 1);
        vg8 += __shfl_xor_sync(0xffffffffu, vg8, 2);
        if (wa == 1 && q == 0) { VX[g] = vg; VX[8+g] = vg8; }
        bar_pair(barid);                             // (3) g2 + VX complete
        if (wa == 0 && q == 0) {
            float c3 = CON[544];
            if (oka) out[ra*13] = vg + VX[g] + c3;
            if (okb) out[rb*13] = vg8 + VX[8+g] + c3;
        }

        // ---- B2: r1 = g2*W2 ; g1 = r1*(1-V1^2): read a -> write b ----
#pragma unroll
        for (int j = 0; j < 16; ++j) {
            uint2 v = ACTa[j*32 + l];
            A[2*j] = v.x; A[2*j+1] = v.y;
        }
#pragma unroll
        for (int i = 0; i < 8; ++i) { c[i][0]=0.f; c[i][1]=0.f; c[i][2]=0.f; c[i][3]=0.f; }
#pragma unroll
        for (int kt = 0; kt < 8; ++kt)
#pragma unroll
            for (int i = 0; i < 8; ++i)
                mma16816(c[i], &A[kt*4], W2B[(kt*16 + nt0 + i)*32 + l]);
#pragma unroll
        for (int i = 0; i < 8; ++i) {
            float2 va = h22f2(V1k[2*i]), vb = h22f2(V1k[2*i+1]);
            uint2 u;
            u.x = f2h2(c[i][0]*(1.f - va.x*va.x), c[i][1]*(1.f - va.y*va.y));
            u.y = f2h2(c[i][2]*(1.f - vb.x*vb.x), c[i][3]*(1.f - vb.y*vb.y));
            ACTb[(nt0 + i)*32 + l] = u;
        }
        bar_pair(barid);                             // (4) g1 complete

        // ---- B1: r0 = g1*W1 ; g0 = r0*(1-V0^2): read b -> write a ----
#pragma unroll
        for (int j = 0; j < 16; ++j) {
            uint2 v = ACTb[j*32 + l];
            A[2*j] = v.x; A[2*j+1] = v.y;
        }
#pragma unroll
        for (int i = 0; i < 8; ++i) { c[i][0]=0.f; c[i][1]=0.f; c[i][2]=0.f; c[i][3]=0.f; }
#pragma unroll
        for (int kt = 0; kt < 8; ++kt)
#pragma unroll
            for (int i = 0; i < 8; ++i)
                mma16816(c[i], &A[kt*4], W1B[(kt*16 + nt0 + i)*32 + l]);
#pragma unroll
        for (int i = 0; i < 8; ++i) {
            float2 va = h22f2(V0k[2*i]), vb = h22f2(V0k[2*i+1]);
            uint2 u;
            u.x = f2h2(c[i][0]*(1.f - va.x*va.x), c[i][1]*(1.f - va.y*va.y));
            u.y = f2h2(c[i][2]*(1.f - vb.x*vb.x), c[i][3]*(1.f - vb.y*vb.y));
            ACTa[(nt0 + i)*32 + l] = u;
        }
        bar_pair(barid);                             // (5) g0 complete

        // ---- J: g0*W0 -> [16x12]; warp wa does n-tile wa: read a ----
#pragma unroll
        for (int j = 0; j < 16; ++j) {
            uint2 v = ACTa[j*32 + l];
            A[2*j] = v.x; A[2*j+1] = v.y;
        }
        {
            float cj[4] = {0.f, 0.f, 0.f, 0.f};
#pragma unroll
            for (int kt = 0; kt < 8; ++kt)
                mma16816(cj, &A[kt*4], W0B[(kt*2 + wa)*32 + l]);
            int cb = 8*wa + 2*q;
            if (cb < NS) {
                float iv0 = INVS[cb], iv1 = INVS[cb+1];
                if (oka) {
                    out[ra*13 + 1 + cb]     = cj[0]*iv0;
                    out[ra*13 + 1 + cb + 1] = cj[1]*iv1;
                }
                if (okb) {
                    out[rb*13 + 1 + cb]     = cj[2]*iv0;
                    out[rb*13 + 1 + cb + 1] = cj[3]*iv1;
                }
            }
        }
        bar_pair(barid);                             // (6) J reads done before next G0
    }
}

extern "C" void kernel_launch(void* const* d_in, const int* in_sizes, int n_in,
                              void* d_out, int out_size)
{
    const float* state  = (const float*)d_in[0];
    const float* safe_m = (const float*)d_in[1];
    const float* safe_l = (const float*)d_in[2];
    const float* W0     = (const float*)d_in[3];
    const float* b0     = (const float*)d_in[4];
    const float* W1     = (const float*)d_in[5];
    const float* b1     = (const float*)d_in[6];
    const float* W2     = (const float*)d_in[7];
    const float* b2     = (const float*)d_in[8];
    const float* W3     = (const float*)d_in[9];
    const float* b3     = (const float*)d_in[10];
    const float* Wout   = (const float*)d_in[11];
    const float* bout   = (const float*)d_in[12];
    float* out = (float*)d_out;

    int nb = in_sizes[0] / NS;

    cudaFuncSetAttribute(mlp_kernel, cudaFuncAttributeMaxDynamicSharedMemorySize,
                         SMEM_BYTES);

    init_kernel<<<1, HID>>>(W3, b3, Wout, bout);
    mlp_kernel<<<GRID, THREADS, SMEM_BYTES>>>(
        state, safe_m, safe_l, W0, b0, W1, b1, W2, b2, out, nb);
}

// round 13
// speedup vs baseline: 2.8229x; 1.0106x over previous
#include <cuda_runtime.h>
#include <cuda_fp16.h>

#define HID 128
#define NS  12
#define NW  28
#define TEAMS (NW/4)
#define THREADS (NW*32)
#define GRID 148
#define MROWS 16

typedef unsigned u32;

// ---- SMEM layout (bytes) ----
#define OFF_W1F 0
#define OFF_W1B 32768
#define OFF_W2F 65536
#define OFF_W2B 98304
#define OFF_W0F 131072
#define OFF_W0B 135168
#define OFF_CON 139264
#define OFF_PB  141568
#define PBSTRIDE 8448                // ACTa 4096 | ACTb 4096 | VX 256
#define SMEM_BYTES (OFF_PB + TEAMS*PBSTRIDE)   // 200704

__device__ __forceinline__ float ftanh(float x)
{
    float e = __expf(2.0f * x);
    return 1.0f - __fdividef(2.0f, e + 1.0f);
}
__device__ __forceinline__ u32 f2h2(float a, float b)
{
    __half2 h = __floats2half2_rn(a, b);
    return *(u32*)&h;
}
__device__ __forceinline__ float2 h22f2(u32 u)
{
    return __half22float2(*(__half2*)&u);
}
__device__ __forceinline__ void mma16816(float c[4], const u32* a, uint2 b)
{
    asm volatile(
        "mma.sync.aligned.m16n8k16.row.col.f32.f16.f16.f32 "
        "{%0,%1,%2,%3}, {%4,%5,%6,%7}, {%8,%9}, {%0,%1,%2,%3};\n"
        : "+f"(c[0]), "+f"(c[1]), "+f"(c[2]), "+f"(c[3])
        : "r"(a[0]), "r"(a[1]), "r"(a[2]), "r"(a[3]), "r"(b.x), "r"(b.y));
}
__device__ __forceinline__ void bar_team(int id)
{
    asm volatile("bar.sync %0, 128;" :: "r"(id) : "memory");
}

__global__ __launch_bounds__(THREADS, 1)
void mlp_kernel(const float* __restrict__ state,
                const float* __restrict__ safe_m, const float* __restrict__ safe_l,
                const float* __restrict__ W0, const float* __restrict__ b0,
                const float* __restrict__ W1, const float* __restrict__ b1,
                const float* __restrict__ W2, const float* __restrict__ b2,
                const float* __restrict__ W3, const float* __restrict__ b3,
                const float* __restrict__ Wout, const float* __restrict__ bout,
                float* __restrict__ out, int nb)
{
    extern __shared__ char smem[];
    uint2* W1F = (uint2*)(smem + OFF_W1F);
    uint2* W1B = (uint2*)(smem + OFF_W1B);
    uint2* W2F = (uint2*)(smem + OFF_W2F);
    uint2* W2B = (uint2*)(smem + OFF_W2B);
    uint2* W0F = (uint2*)(smem + OFF_W0F);
    uint2* W0B = (uint2*)(smem + OFF_W0B);
    float* CON = (float*)(smem + OFF_CON);
    float* PRT = (float*)(smem + OFF_PB);      // init-time scratch (c3 partials)

    int tid = threadIdx.x;

    // ---- constants + R3 (computed per-CTA; coalesced W3 column reads) ----
    if (tid < HID) {
        CON[0   + tid] = b0[tid];
        CON[128 + tid] = b1[tid];
        CON[256 + tid] = b2[tid];
        float acc = 0.f;
#pragma unroll 4
        for (int j = 0; j < HID; ++j) acc = fmaf(Wout[j], W3[j*HID + tid], acc);
        CON[384 + tid] = acc;                  // R3
        PRT[tid] = Wout[tid] * b3[tid];        // c3 partial
    }
    if (tid < NS) {
        float m = safe_m[tid], lo = safe_l[tid];
        CON[512 + tid] = 0.5f * (m + lo);
        CON[528 + tid] = 2.0f / (m - lo);
    }

    // ---- build W1/W2 fragments directly from global (L2-broadcast) ----
    for (int e = tid; e < 128*32; e += THREADS) {
        int T = e >> 5, lf = e & 31;
        int kt = T >> 4, nt = T & 15, qf = lf & 3, gf = lf >> 2;
        int n = 8*nt + gf, k = 16*kt + 2*qf;
        {
            float2 wlo = *(const float2*)&W1[n*HID + k];
            float2 whi = *(const float2*)&W1[n*HID + k + 8];
            uint2 uf; uf.x = f2h2(wlo.x, wlo.y); uf.y = f2h2(whi.x, whi.y);
            uint2 ub;
            ub.x = f2h2(W1[k*HID + n],     W1[(k+1)*HID + n]);
            ub.y = f2h2(W1[(k+8)*HID + n], W1[(k+9)*HID + n]);
            W1F[e] = uf; W1B[e] = ub;
        }
        {
            float2 wlo = *(const float2*)&W2[n*HID + k];
            float2 whi = *(const float2*)&W2[n*HID + k + 8];
            uint2 uf; uf.x = f2h2(wlo.x, wlo.y); uf.y = f2h2(whi.x, whi.y);
            uint2 ub;
            ub.x = f2h2(W2[k*HID + n],     W2[(k+1)*HID + n]);
            ub.y = f2h2(W2[(k+8)*HID + n], W2[(k+9)*HID + n]);
            W2F[e] = uf; W2B[e] = ub;
        }
    }
    for (int e = tid; e < 16*32; e += THREADS) {
        int T = e >> 5, lf = e & 31, qf = lf & 3, gf = lf >> 2;
        {   // W0F: fwd GEMM0, T = nt
            int n = 8*T + gf, k = 2*qf;
            uint2 u;
            u.x = f2h2(W0[n*NS + k], W0[n*NS + k + 1]);
            u.y = (qf < 2) ? f2h2(W0[n*NS + k + 8], W0[n*NS + k + 9]) : 0u;
            W0F[e] = u;
        }
        {   // W0B: final J, kt=T>>1, nt=T&1
            int kt = T >> 1, ntb = T & 1;
            int n = 8*ntb + gf, k = 16*kt + 2*qf;
            float w00 = 0.f, w01 = 0.f, w10 = 0.f, w11 = 0.f;
            if (n < NS) {
                w00 = W0[k*NS + n];     w01 = W0[(k+1)*NS + n];
                w10 = W0[(k+8)*NS + n]; w11 = W0[(k+9)*NS + n];
            }
            uint2 u; u.x = f2h2(w00, w01); u.y = f2h2(w10, w11);
            W0B[e] = u;
        }
    }
    __syncthreads();
    if (tid == 0) {
        float c = bout[0];
#pragma unroll 4
        for (int i = 0; i < HID; i += 4) {
            float4 p = *(const float4*)&PRT[i];
            c += p.x + p.y + p.z + p.w;
        }
        CON[544] = c;
    }
    __syncthreads();

    int w = tid >> 5, l = tid & 31, q = l & 3, g = l >> 2;
    int team = w >> 2, wq = w & 3;
    char* PB = smem + OFF_PB + team*PBSTRIDE;
    uint2* ACTa = (uint2*)PB;             // [16 nt][32 lanes]
    uint2* ACTb = (uint2*)(PB + 4096);
    float* VX   = (float*)(PB + 8192);    // 64 floats
    int barid = team + 1;

    const float* B0S = CON;
    const float* B1S = CON + 128;
    const float* B2S = CON + 256;
    const float* R3S = CON + 384;
    const float* CENS = CON + 512;
    const float* INVS = CON + 528;

    int nt0 = 4*wq;                       // this warp's 4 n-tiles

    int ntask = (nb + MROWS - 1) / MROWS;
    for (int task = blockIdx.x + GRID*team; task < ntask; task += GRID*TEAMS) {
        int base = task * MROWS;
        int ra = base + g, rb = base + g + 8;
        bool oka = ra < nb, okb = rb < nb;

        u32 A[16];
        u32 V0k[8], V1k[8];               // own 4 nt of V0/V1 (fp16 pairs)
        float c[4][4];

        // ---- X load + normalize -> A[0..3] ----
        {
            float2 z2 = make_float2(0.f, 0.f);
            float2 xa = oka ? *(const float2*)&state[ra*NS + 2*q] : z2;
            float2 xb = okb ? *(const float2*)&state[rb*NS + 2*q] : z2;
            float2 xc = z2, xd = z2;
            float c0v = CENS[2*q], c1v = CENS[2*q+1];
            float i0v = INVS[2*q], i1v = INVS[2*q+1];
            xa.x = (xa.x - c0v)*i0v; xa.y = (xa.y - c1v)*i1v;
            xb.x = (xb.x - c0v)*i0v; xb.y = (xb.y - c1v)*i1v;
            if (q < 2) {
                if (oka) xc = *(const float2*)&state[ra*NS + 2*q + 8];
                if (okb) xd = *(const float2*)&state[rb*NS + 2*q + 8];
                float c2v = CENS[2*q+8], c3v = CENS[2*q+9];
                float i2v = INVS[2*q+8], i3v = INVS[2*q+9];
                xc.x = (xc.x - c2v)*i2v; xc.y = (xc.y - c3v)*i3v;
                xd.x = (xd.x - c2v)*i2v; xd.y = (xd.y - c3v)*i3v;
            }
            A[0] = f2h2(xa.x, xa.y);
            A[1] = f2h2(xb.x, xb.y);
            A[2] = f2h2(xc.x, xc.y);
            A[3] = f2h2(xd.x, xd.y);
        }

        // ---- G0: V0 = tanh(X*W0^T + b0) -> ACTa + V0k ----
#pragma unroll
        for (int i = 0; i < 4; ++i) {
            int nt = nt0 + i;
            float2 bp = *(const float2*)&B0S[8*nt + 2*q];
            c[i][0] = bp.x; c[i][1] = bp.y; c[i][2] = bp.x; c[i][3] = bp.y;
            mma16816(c[i], &A[0], W0F[nt*32 + l]);
        }
#pragma unroll
        for (int i = 0; i < 4; ++i) {
            uint2 u;
            u.x = f2h2(ftanh(c[i][0]), ftanh(c[i][1]));
            u.y = f2h2(ftanh(c[i][2]), ftanh(c[i][3]));
            ACTa[(nt0 + i)*32 + l] = u;
            V0k[2*i] = u.x; V0k[2*i+1] = u.y;
        }
        bar_team(barid);                             // (1) ACTa complete

        // ---- G1: V1 = tanh(V0*W1^T + b1): read a -> write b + V1k ----
#pragma unroll
        for (int i = 0; i < 4; ++i) {
            float2 bp = *(const float2*)&B1S[8*(nt0+i) + 2*q];
            c[i][0] = bp.x; c[i][1] = bp.y; c[i][2] = bp.x; c[i][3] = bp.y;
        }
#pragma unroll
        for (int h = 0; h < 2; ++h) {
#pragma unroll
            for (int j = 0; j < 8; ++j) {
                uint2 v = ACTa[(8*h + j)*32 + l];
                A[2*j] = v.x; A[2*j+1] = v.y;
            }
#pragma unroll
            for (int kt = 0; kt < 4; ++kt)
#pragma unroll
                for (int i = 0; i < 4; ++i)
                    mma16816(c[i], &A[kt*4], W1F[((4*h + kt)*16 + nt0 + i)*32 + l]);
        }
#pragma unroll
        for (int i = 0; i < 4; ++i) {
            uint2 u;
            u.x = f2h2(ftanh(c[i][0]), ftanh(c[i][1]));
            u.y = f2h2(ftanh(c[i][2]), ftanh(c[i][3]));
            ACTb[(nt0 + i)*32 + l] = u;
            V1k[2*i] = u.x; V1k[2*i+1] = u.y;
        }
        bar_team(barid);                             // (2) ACTb complete

        // ---- G2: V2 = tanh(V1*W2^T + b2); vout partial; g2: read b -> write a ----
#pragma unroll
        for (int i = 0; i < 4; ++i) {
            float2 bp = *(const float2*)&B2S[8*(nt0+i) + 2*q];
            c[i][0] = bp.x; c[i][1] = bp.y; c[i][2] = bp.x; c[i][3] = bp.y;
        }
#pragma unroll
        for (int h = 0; h < 2; ++h) {
#pragma unroll
            for (int j = 0; j < 8; ++j) {
                uint2 v = ACTb[(8*h + j)*32 + l];
                A[2*j] = v.x; A[2*j+1] = v.y;
            }
#pragma unroll
            for (int kt = 0; kt < 4; ++kt)
#pragma unroll
                for (int i = 0; i < 4; ++i)
                    mma16816(c[i], &A[kt*4], W2F[((4*h + kt)*16 + nt0 + i)*32 + l]);
        }
        float vg = 0.f, vg8 = 0.f;
#pragma unroll
        for (int i = 0; i < 4; ++i) {
            int nt = nt0 + i;
            float2 r3p = *(const float2*)&R3S[8*nt + 2*q];
            float t0 = ftanh(c[i][0]), t1 = ftanh(c[i][1]);
            float t2 = ftanh(c[i][2]), t3 = ftanh(c[i][3]);
            vg  += r3p.x*t0 + r3p.y*t1;
            vg8 += r3p.x*t2 + r3p.y*t3;
            uint2 u;
            u.x = f2h2(r3p.x*(1.f - t0*t0), r3p.y*(1.f - t1*t1));
            u.y = f2h2(r3p.x*(1.f - t2*t2), r3p.y*(1.f - t3*t3));
            ACTa[nt*32 + l] = u;
        }
        vg  += __shfl_xor_sync(0xffffffffu, vg, 1);
        vg  += __shfl_xor_sync(0xffffffffu, vg, 2);
        vg8 += __shfl_xor_sync(0xffffffffu, vg8, 1);
        vg8 += __shfl_xor_sync(0xffffffffu, vg8, 2);
        if (wq != 0 && q == 0) { VX[wq*16 + g] = vg; VX[wq*16 + 8 + g] = vg8; }
        bar_team(barid);                             // (3) g2 + VX complete
        if (wq == 0 && q == 0) {
            float c3 = CON[544];
            if (oka) out[ra*13]   = vg  + VX[16+g]   + VX[32+g]   + VX[48+g]   + c3;
            if (okb) out[rb*13]   = vg8 + VX[16+8+g] + VX[32+8+g] + VX[48+8+g] + c3;
        }

        // ---- B2: r1 = g2*W2 ; g1 = r1*(1-V1^2): read a -> write b ----
#pragma unroll
        for (int i = 0; i < 4; ++i) { c[i][0]=0.f; c[i][1]=0.f; c[i][2]=0.f; c[i][3]=0.f; }
#pragma unroll
        for (int h = 0; h < 2; ++h) {
#pragma unroll
            for (int j = 0; j < 8; ++j) {
                uint2 v = ACTa[(8*h + j)*32 + l];
                A[2*j] = v.x; A[2*j+1] = v.y;
            }
#pragma unroll
            for (int kt = 0; kt < 4; ++kt)
#pragma unroll
                for (int i = 0; i < 4; ++i)
                    mma16816(c[i], &A[kt*4], W2B[((4*h + kt)*16 + nt0 + i)*32 + l]);
        }
#pragma unroll
        for (int i = 0; i < 4; ++i) {
            float2 va = h22f2(V1k[2*i]), vb = h22f2(V1k[2*i+1]);
            uint2 u;
            u.x = f2h2(c[i][0]*(1.f - va.x*va.x), c[i][1]*(1.f - va.y*va.y));
            u.y = f2h2(c[i][2]*(1.f - vb.x*vb.x), c[i][3]*(1.f - vb.y*vb.y));
            ACTb[(nt0 + i)*32 + l] = u;
        }
        bar_team(barid);                             // (4) g1 complete

        // ---- B1: r0 = g1*W1 ; g0 = r0*(1-V0^2): read b -> write a ----
#pragma unroll
        for (int i = 0; i < 4; ++i) { c[i][0]=0.f; c[i][1]=0.f; c[i][2]=0.f; c[i][3]=0.f; }
#pragma unroll
        for (int h = 0; h < 2; ++h) {
#pragma unroll
            for (int j = 0; j < 8; ++j) {
                uint2 v = ACTb[(8*h + j)*32 + l];
                A[2*j] = v.x; A[2*j+1] = v.y;
            }
#pragma unroll
            for (int kt = 0; kt < 4; ++kt)
#pragma unroll
                for (int i = 0; i < 4; ++i)
                    mma16816(c[i], &A[kt*4], W1B[((4*h + kt)*16 + nt0 + i)*32 + l]);
        }
#pragma unroll
        for (int i = 0; i < 4; ++i) {
            float2 va = h22f2(V0k[2*i]), vb = h22f2(V0k[2*i+1]);
            uint2 u;
            u.x = f2h2(c[i][0]*(1.f - va.x*va.x), c[i][1]*(1.f - va.y*va.y));
            u.y = f2h2(c[i][2]*(1.f - vb.x*vb.x), c[i][3]*(1.f - vb.y*vb.y));
            ACTa[(nt0 + i)*32 + l] = u;
        }
        bar_team(barid);                             // (5) g0 complete

        // ---- J: g0*W0 -> [16x12]; warps 0,1 each do one n-tile ----
        if (wq < 2) {
            float cj[4] = {0.f, 0.f, 0.f, 0.f};
#pragma unroll
            for (int h = 0; h < 2; ++h) {
#pragma unroll
                for (int j = 0; j < 8; ++j) {
                    uint2 v = ACTa[(8*h + j)*32 + l];
                    A[2*j] = v.x; A[2*j+1] = v.y;
                }
#pragma unroll
                for (int kt = 0; kt < 4; ++kt)
                    mma16816(cj, &A[kt*4], W0B[((4*h + kt)*2 + wq)*32 + l]);
            }
            int cb = 8*wq + 2*q;
            if (cb < NS) {
                float iv0 = INVS[cb], iv1 = INVS[cb+1];
                if (oka) {
                    out[ra*13 + 1 + cb]     = cj[0]*iv0;
                    out[ra*13 + 1 + cb + 1] = cj[1]*iv1;
                }
                if (okb) {
                    out[rb*13 + 1 + cb]     = cj[2]*iv0;
                    out[rb*13 + 1 + cb + 1] = cj[3]*iv1;
                }
            }
        }
        bar_team(barid);                             // (6) J reads done before next G0
    }
}

extern "C" void kernel_launch(void* const* d_in, const int* in_sizes, int n_in,
                              void* d_out, int out_size)
{
    const float* state  = (const float*)d_in[0];
    const float* safe_m = (const float*)d_in[1];
    const float* safe_l = (const float*)d_in[2];
    const float* W0     = (const float*)d_in[3];
    const float* b0     = (const float*)d_in[4];
    const float* W1     = (const float*)d_in[5];
    const float* b1     = (const float*)d_in[6];
    const float* W2     = (const float*)d_in[7];
    const float* b2     = (const float*)d_in[8];
    const float* W3     = (const float*)d_in[9];
    const float* b3     = (const float*)d_in[10];
    const float* Wout   = (const float*)d_in[11];
    const float* bout   = (const float*)d_in[12];
    float* out = (float*)d_out;

    int nb = in_sizes[0] / NS;

    cudaFuncSetAttribute(mlp_kernel, cudaFuncAttributeMaxDynamicSharedMemorySize,
                         SMEM_BYTES);

    mlp_kernel<<<GRID, THREADS, SMEM_BYTES>>>(
        state, safe_m, safe_l, W0, b0, W1, b1, W2, b2, W3, b3, Wout, bout,
        out, nb);
}

// round 14
// speedup vs baseline: 3.0497x; 1.0804x over previous
#include <cuda_runtime.h>
#include <cuda_fp16.h>

#define HID 128
#define NS  12
#define NW  14
#define PAIRS (NW/2)
#define THREADS (NW*32)
#define GRID 148
#define MROWS 16

typedef unsigned u32;

// ---- SMEM layout (bytes) ----
#define OFF_W1F 0
#define OFF_W1B 32768
#define OFF_W2F 65536
#define OFF_W2B 98304
#define OFF_W0F 131072
#define OFF_W0B 135168
#define OFF_CON 139264
#define OFF_PB  141568
#define PBSTRIDE 8256                // ACTa 4096 | ACTb 4096 | VX 64
#define SMEM_BYTES (OFF_PB + PAIRS*PBSTRIDE)   // 199360

__device__ __forceinline__ float ftanh(float x)
{
    float e = __expf(2.0f * x);
    return 1.0f - __fdividef(2.0f, e + 1.0f);
}
__device__ __forceinline__ u32 f2h2(float a, float b)
{
    __half2 h = __floats2half2_rn(a, b);
    return *(u32*)&h;
}
__device__ __forceinline__ float2 h22f2(u32 u)
{
    return __half22float2(*(__half2*)&u);
}
__device__ __forceinline__ void mma16816(float c[4], const u32* a, uint2 b)
{
    asm volatile(
        "mma.sync.aligned.m16n8k16.row.col.f32.f16.f16.f32 "
        "{%0,%1,%2,%3}, {%4,%5,%6,%7}, {%8,%9}, {%0,%1,%2,%3};\n"
        : "+f"(c[0]), "+f"(c[1]), "+f"(c[2]), "+f"(c[3])
        : "r"(a[0]), "r"(a[1]), "r"(a[2]), "r"(a[3]), "r"(b.x), "r"(b.y));
}
__device__ __forceinline__ void bar_pair(int id)
{
    asm volatile("bar.sync %0, 64;" :: "r"(id) : "memory");
}

__global__ __launch_bounds__(THREADS, 1)
void mlp_kernel(const float* __restrict__ state,
                const float* __restrict__ safe_m, const float* __restrict__ safe_l,
                const float* __restrict__ W0, const float* __restrict__ b0,
                const float* __restrict__ W1, const float* __restrict__ b1,
                const float* __restrict__ W2, const float* __restrict__ b2,
                const float* __restrict__ W3, const float* __restrict__ b3,
                const float* __restrict__ Wout, const float* __restrict__ bout,
                float* __restrict__ out, int nb)
{
    extern __shared__ char smem[];
    uint2* W1F = (uint2*)(smem + OFF_W1F);
    uint2* W1B = (uint2*)(smem + OFF_W1B);
    uint2* W2F = (uint2*)(smem + OFF_W2F);
    uint2* W2B = (uint2*)(smem + OFF_W2B);
    uint2* W0F = (uint2*)(smem + OFF_W0F);
    uint2* W0B = (uint2*)(smem + OFF_W0B);
    float* CON = (float*)(smem + OFF_CON);
    float* PRT = (float*)(smem + OFF_PB);      // init-time scratch (c3 partials)

    int tid = threadIdx.x;

    // ---- constants + R3 (per-CTA; coalesced W3 column reads) ----
    if (tid < HID) {
        CON[0   + tid] = b0[tid];
        CON[128 + tid] = b1[tid];
        CON[256 + tid] = b2[tid];
        float acc = 0.f;
#pragma unroll 4
        for (int j = 0; j < HID; ++j) acc = fmaf(Wout[j], W3[j*HID + tid], acc);
        CON[384 + tid] = acc;                  // R3
        PRT[tid] = Wout[tid] * b3[tid];        // c3 partial
    }
    if (tid < NS) {
        float m = safe_m[tid], lo = safe_l[tid];
        CON[512 + tid] = 0.5f * (m + lo);
        CON[528 + tid] = 2.0f / (m - lo);
    }

    // ---- build W1/W2 fragments directly from global (L2-broadcast) ----
    for (int e = tid; e < 128*32; e += THREADS) {
        int T = e >> 5, lf = e & 31;
        int kt = T >> 4, nt = T & 15, qf = lf & 3, gf = lf >> 2;
        int n = 8*nt + gf, k = 16*kt + 2*qf;
        {
            float2 wlo = *(const float2*)&W1[n*HID + k];
            float2 whi = *(const float2*)&W1[n*HID + k + 8];
            uint2 uf; uf.x = f2h2(wlo.x, wlo.y); uf.y = f2h2(whi.x, whi.y);
            uint2 ub;
            ub.x = f2h2(W1[k*HID + n],     W1[(k+1)*HID + n]);
            ub.y = f2h2(W1[(k+8)*HID + n], W1[(k+9)*HID + n]);
            W1F[e] = uf; W1B[e] = ub;
        }
        {
            float2 wlo = *(const float2*)&W2[n*HID + k];
            float2 whi = *(const float2*)&W2[n*HID + k + 8];
            uint2 uf; uf.x = f2h2(wlo.x, wlo.y); uf.y = f2h2(whi.x, whi.y);
            uint2 ub;
            ub.x = f2h2(W2[k*HID + n],     W2[(k+1)*HID + n]);
            ub.y = f2h2(W2[(k+8)*HID + n], W2[(k+9)*HID + n]);
            W2F[e] = uf; W2B[e] = ub;
        }
    }
    for (int e = tid; e < 16*32; e += THREADS) {
        int T = e >> 5, lf = e & 31, qf = lf & 3, gf = lf >> 2;
        {   // W0F: fwd GEMM0, T = nt
            int n = 8*T + gf, k = 2*qf;
            uint2 u;
            u.x = f2h2(W0[n*NS + k], W0[n*NS + k + 1]);
            u.y = (qf < 2) ? f2h2(W0[n*NS + k + 8], W0[n*NS + k + 9]) : 0u;
            W0F[e] = u;
        }
        {   // W0B: final J, kt=T>>1, nt=T&1
            int kt = T >> 1, ntb = T & 1;
            int n = 8*ntb + gf, k = 16*kt + 2*qf;
            float w00 = 0.f, w01 = 0.f, w10 = 0.f, w11 = 0.f;
            if (n < NS) {
                w00 = W0[k*NS + n];     w01 = W0[(k+1)*NS + n];
                w10 = W0[(k+8)*NS + n]; w11 = W0[(k+9)*NS + n];
            }
            uint2 u; u.x = f2h2(w00, w01); u.y = f2h2(w10, w11);
            W0B[e] = u;
        }
    }
    __syncthreads();
    if (tid == 0) {
        float c = bout[0];
#pragma unroll 4
        for (int i = 0; i < HID; i += 4) {
            float4 p = *(const float4*)&PRT[i];
            c += p.x + p.y + p.z + p.w;
        }
        CON[544] = c;
    }
    __syncthreads();

    int w = tid >> 5, l = tid & 31, q = l & 3, g = l >> 2;
    int pair = w >> 1, wa = w & 1;
    char* PB = smem + OFF_PB + pair*PBSTRIDE;
    uint2* ACTa = (uint2*)PB;             // [16 nt][32 lanes]
    uint2* ACTb = (uint2*)(PB + 4096);
    float* VX   = (float*)(PB + 8192);
    int barid = pair + 1;

    const float* B0S = CON;
    const float* B1S = CON + 128;
    const float* B2S = CON + 256;
    const float* R3S = CON + 384;
    const float* CENS = CON + 512;
    const float* INVS = CON + 528;

    int nt0 = 8*wa;                       // this warp's n-tile half

    int ntask = (nb + MROWS - 1) / MROWS;
    for (int task = blockIdx.x + GRID*pair; task < ntask; task += GRID*PAIRS) {
        int base = task * MROWS;
        int ra = base + g, rb = base + g + 8;
        bool oka = ra < nb, okb = rb < nb;

        u32 A[32];
        u32 V0k[16], V1k[16];             // own-half V0/V1 (fp16 pairs), register-resident
        float c[8][4];

        // ---- X load + normalize -> A[0..3] ----
        {
            float2 z2 = make_float2(0.f, 0.f);
            float2 xa = oka ? *(const float2*)&state[ra*NS + 2*q] : z2;
            float2 xb = okb ? *(const float2*)&state[rb*NS + 2*q] : z2;
            float2 xc = z2, xd = z2;
            float c0v = CENS[2*q], c1v = CENS[2*q+1];
            float i0v = INVS[2*q], i1v = INVS[2*q+1];
            xa.x = (xa.x - c0v)*i0v; xa.y = (xa.y - c1v)*i1v;
            xb.x = (xb.x - c0v)*i0v; xb.y = (xb.y - c1v)*i1v;
            if (q < 2) {
                if (oka) xc = *(const float2*)&state[ra*NS + 2*q + 8];
                if (okb) xd = *(const float2*)&state[rb*NS + 2*q + 8];
                float c2v = CENS[2*q+8], c3v = CENS[2*q+9];
                float i2v = INVS[2*q+8], i3v = INVS[2*q+9];
                xc.x = (xc.x - c2v)*i2v; xc.y = (xc.y - c3v)*i3v;
                xd.x = (xd.x - c2v)*i2v; xd.y = (xd.y - c3v)*i3v;
            }
            A[0] = f2h2(xa.x, xa.y);
            A[1] = f2h2(xb.x, xb.y);
            A[2] = f2h2(xc.x, xc.y);
            A[3] = f2h2(xd.x, xd.y);
        }

        // ---- G0: V0 = tanh(X*W0^T + b0) -> ACTa + V0k ----
#pragma unroll
        for (int i = 0; i < 8; ++i) {
            int nt = nt0 + i;
            float2 bp = *(const float2*)&B0S[8*nt + 2*q];
            c[i][0] = bp.x; c[i][1] = bp.y; c[i][2] = bp.x; c[i][3] = bp.y;
            mma16816(c[i], &A[0], W0F[nt*32 + l]);
        }
#pragma unroll
        for (int i = 0; i < 8; ++i) {
            uint2 u;
            u.x = f2h2(ftanh(c[i][0]), ftanh(c[i][1]));
            u.y = f2h2(ftanh(c[i][2]), ftanh(c[i][3]));
            ACTa[(nt0 + i)*32 + l] = u;
            V0k[2*i] = u.x; V0k[2*i+1] = u.y;
        }
        bar_pair(barid);                             // (1) ACTa complete

        // ---- G1: V1 = tanh(V0*W1^T + b1): read a -> write b + V1k ----
#pragma unroll
        for (int j = 0; j < 16; ++j) {
            uint2 v = ACTa[j*32 + l];
            A[2*j] = v.x; A[2*j+1] = v.y;
        }
#pragma unroll
        for (int i = 0; i < 8; ++i) {
            float2 bp = *(const float2*)&B1S[8*(nt0+i) + 2*q];
            c[i][0] = bp.x; c[i][1] = bp.y; c[i][2] = bp.x; c[i][3] = bp.y;
        }
#pragma unroll
        for (int kt = 0; kt < 8; ++kt)
#pragma unroll
            for (int i = 0; i < 8; ++i)
                mma16816(c[i], &A[kt*4], W1F[(kt*16 + nt0 + i)*32 + l]);
#pragma unroll
        for (int i = 0; i < 8; ++i) {
            uint2 u;
            u.x = f2h2(ftanh(c[i][0]), ftanh(c[i][1]));
            u.y = f2h2(ftanh(c[i][2]), ftanh(c[i][3]));
            ACTb[(nt0 + i)*32 + l] = u;
            V1k[2*i] = u.x; V1k[2*i+1] = u.y;
        }
        bar_pair(barid);                             // (2) ACTb complete

        // ---- G2: V2 = tanh(V1*W2^T + b2); vout partial; g2: read b -> write a ----
#pragma unroll
        for (int j = 0; j < 16; ++j) {
            uint2 v = ACTb[j*32 + l];
            A[2*j] = v.x; A[2*j+1] = v.y;
        }
#pragma unroll
        for (int i = 0; i < 8; ++i) {
            float2 bp = *(const float2*)&B2S[8*(nt0+i) + 2*q];
            c[i][0] = bp.x; c[i][1] = bp.y; c[i][2] = bp.x; c[i][3] = bp.y;
        }
#pragma unroll
        for (int kt = 0; kt < 8; ++kt)
#pragma unroll
            for (int i = 0; i < 8; ++i)
                mma16816(c[i], &A[kt*4], W2F[(kt*16 + nt0 + i)*32 + l]);
        float vg = 0.f, vg8 = 0.f;
#pragma unroll
        for (int i = 0; i < 8; ++i) {
            int nt = nt0 + i;
            float2 r3p = *(const float2*)&R3S[8*nt + 2*q];
            float t0 = ftanh(c[i][0]), t1 = ftanh(c[i][1]);
            float t2 = ftanh(c[i][2]), t3 = ftanh(c[i][3]);
            vg  += r3p.x*t0 + r3p.y*t1;
            vg8 += r3p.x*t2 + r3p.y*t3;
            uint2 u;
            u.x = f2h2(r3p.x*(1.f - t0*t0), r3p.y*(1.f - t1*t1));
            u.y = f2h2(r3p.x*(1.f - t2*t2), r3p.y*(1.f - t3*t3));
            ACTa[nt*32 + l] = u;
        }
        vg  += __shfl_xor_sync(0xffffffffu, vg, 1);
        vg  += __shfl_xor_sync(0xffffffffu, vg, 2);
        vg8 += __shfl_xor_sync(0xffffffffu, vg8, 1);
        vg8 += __shfl_xor_sync(0xffffffffu, vg8, 2);
        if (wa == 1 && q == 0) { VX[g] = vg; VX[8+g] = vg8; }
        bar_pair(barid);                             // (3) g2 + VX complete
        if (wa == 0 && q == 0) {
            float c3 = CON[544];
            if (oka) out[ra*13] = vg + VX[g] + c3;
            if (okb) out[rb*13] = vg8 + VX[8+g] + c3;
        }

        // ---- B2: r1 = g2*W2 ; g1 = r1*(1-V1^2): read a -> write b ----
#pragma unroll
        for (int j = 0; j < 16; ++j) {
            uint2 v = ACTa[j*32 + l];
            A[2*j] = v.x; A[2*j+1] = v.y;
        }
#pragma unroll
        for (int i = 0; i < 8; ++i) { c[i][0]=0.f; c[i][1]=0.f; c[i][2]=0.f; c[i][3]=0.f; }
#pragma unroll
        for (int kt = 0; kt < 8; ++kt)
#pragma unroll
            for (int i = 0; i < 8; ++i)
                mma16816(c[i], &A[kt*4], W2B[(kt*16 + nt0 + i)*32 + l]);
#pragma unroll
        for (int i = 0; i < 8; ++i) {
            float2 va = h22f2(V1k[2*i]), vb = h22f2(V1k[2*i+1]);
            uint2 u;
            u.x = f2h2(c[i][0]*(1.f - va.x*va.x), c[i][1]*(1.f - va.y*va.y));
            u.y = f2h2(c[i][2]*(1.f - vb.x*vb.x), c[i][3]*(1.f - vb.y*vb.y));
            ACTb[(nt0 + i)*32 + l] = u;
        }
        bar_pair(barid);                             // (4) g1 complete

        // ---- B1: r0 = g1*W1 ; g0 = r0*(1-V0^2): read b -> write a ----
#pragma unroll
        for (int j = 0; j < 16; ++j) {
            uint2 v = ACTb[j*32 + l];
            A[2*j] = v.x; A[2*j+1] = v.y;
        }
#pragma unroll
        for (int i = 0; i < 8; ++i) { c[i][0]=0.f; c[i][1]=0.f; c[i][2]=0.f; c[i][3]=0.f; }
#pragma unroll
        for (int kt = 0; kt < 8; ++kt)
#pragma unroll
            for (int i = 0; i < 8; ++i)
                mma16816(c[i], &A[kt*4], W1B[(kt*16 + nt0 + i)*32 + l]);
#pragma unroll
        for (int i = 0; i < 8; ++i) {
            float2 va = h22f2(V0k[2*i]), vb = h22f2(V0k[2*i+1]);
            uint2 u;
            u.x = f2h2(c[i][0]*(1.f - va.x*va.x), c[i][1]*(1.f - va.y*va.y));
            u.y = f2h2(c[i][2]*(1.f - vb.x*vb.x), c[i][3]*(1.f - vb.y*vb.y));
            ACTa[(nt0 + i)*32 + l] = u;
        }
        bar_pair(barid);                             // (5) g0 complete

        // ---- J: g0*W0 -> [16x12]; warp wa does n-tile wa: read a ----
#pragma unroll
        for (int j = 0; j < 16; ++j) {
            uint2 v = ACTa[j*32 + l];
            A[2*j] = v.x; A[2*j+1] = v.y;
        }
        {
            float cj[4] = {0.f, 0.f, 0.f, 0.f};
#pragma unroll
            for (int kt = 0; kt < 8; ++kt)
                mma16816(cj, &A[kt*4], W0B[(kt*2 + wa)*32 + l]);
            int cb = 8*wa + 2*q;
            if (cb < NS) {
                float iv0 = INVS[cb], iv1 = INVS[cb+1];
                if (oka) {
                    out[ra*13 + 1 + cb]     = cj[0]*iv0;
                    out[ra*13 + 1 + cb + 1] = cj[1]*iv1;
                }
                if (okb) {
                    out[rb*13 + 1 + cb]     = cj[2]*iv0;
                    out[rb*13 + 1 + cb + 1] = cj[3]*iv1;
                }
            }
        }
        bar_pair(barid);                             // (6) J reads done before next G0
    }
}

extern "C" void kernel_launch(void* const* d_in, const int* in_sizes, int n_in,
                              void* d_out, int out_size)
{
    const float* state  = (const float*)d_in[0];
    const float* safe_m = (const float*)d_in[1];
    const float* safe_l = (const float*)d_in[2];
    const float* W0     = (const float*)d_in[3];
    const float* b0     = (const float*)d_in[4];
    const float* W1     = (const float*)d_in[5];
    const float* b1     = (const float*)d_in[6];
    const float* W2     = (const float*)d_in[7];
    const float* b2     = (const float*)d_in[8];
    const float* W3     = (const float*)d_in[9];
    const float* b3     = (const float*)d_in[10];
    const float* Wout   = (const float*)d_in[11];
    const float* bout   = (const float*)d_in[12];
    float* out = (float*)d_out;

    int nb = in_sizes[0] / NS;

    cudaFuncSetAttribute(mlp_kernel, cudaFuncAttributeMaxDynamicSharedMemorySize,
                         SMEM_BYTES);

    mlp_kernel<<<GRID, THREADS, SMEM_BYTES>>>(
        state, safe_m, safe_l, W0, b0, W1, b1, W2, b2, W3, b3, Wout, bout,
        out, nb);
}

// round 15
// speedup vs baseline: 3.3771x; 1.1073x over previous
#include <cuda_runtime.h>
#include <cuda_fp16.h>

#define HID 128
#define NS  12
#define NW  14
#define PAIRS (NW/2)
#define THREADS (NW*32)
#define GRID 148
#define MROWS 16

typedef unsigned u32;

// ---- SMEM layout (bytes) ----
#define OFF_W1F 0
#define OFF_W1B 32768
#define OFF_W2F 65536
#define OFF_W2B 98304
#define OFF_W0F 131072
#define OFF_W0B 135168
#define OFF_CON 139264
#define OFF_PB  141568
#define PBSTRIDE 8256                // ACTa 4096 | ACTb 4096 | VX 64
#define SMEM_BYTES (OFF_PB + PAIRS*PBSTRIDE)   // 199360

// tanh.approx.f32: 1 MUFU op, err ~2^-11 (same order as fp16 rounding)
__device__ __forceinline__ float ftanh(float x)
{
    float y;
    asm("tanh.approx.f32 %0, %1;" : "=f"(y) : "f"(x));
    return y;
}
__device__ __forceinline__ u32 f2h2(float a, float b)
{
    __half2 h = __floats2half2_rn(a, b);
    return *(u32*)&h;
}
__device__ __forceinline__ float2 h22f2(u32 u)
{
    return __half22float2(*(__half2*)&u);
}
__device__ __forceinline__ void mma16816(float c[4], const u32* a, uint2 b)
{
    asm volatile(
        "mma.sync.aligned.m16n8k16.row.col.f32.f16.f16.f32 "
        "{%0,%1,%2,%3}, {%4,%5,%6,%7}, {%8,%9}, {%0,%1,%2,%3};\n"
        : "+f"(c[0]), "+f"(c[1]), "+f"(c[2]), "+f"(c[3])
        : "r"(a[0]), "r"(a[1]), "r"(a[2]), "r"(a[3]), "r"(b.x), "r"(b.y));
}
__device__ __forceinline__ void bar_pair(int id)
{
    asm volatile("bar.sync %0, 64;" :: "r"(id) : "memory");
}

__global__ __launch_bounds__(THREADS, 1)
void mlp_kernel(const float* __restrict__ state,
                const float* __restrict__ safe_m, const float* __restrict__ safe_l,
                const float* __restrict__ W0, const float* __restrict__ b0,
                const float* __restrict__ W1, const float* __restrict__ b1,
                const float* __restrict__ W2, const float* __restrict__ b2,
                const float* __restrict__ W3, const float* __restrict__ b3,
                const float* __restrict__ Wout, const float* __restrict__ bout,
                float* __restrict__ out, int nb)
{
    extern __shared__ char smem[];
    uint2* W1F = (uint2*)(smem + OFF_W1F);
    uint2* W1B = (uint2*)(smem + OFF_W1B);
    uint2* W2F = (uint2*)(smem + OFF_W2F);
    uint2* W2B = (uint2*)(smem + OFF_W2B);
    uint2* W0F = (uint2*)(smem + OFF_W0F);
    uint2* W0B = (uint2*)(smem + OFF_W0B);
    float* CON = (float*)(smem + OFF_CON);
    float* PRT = (float*)(smem + OFF_PB);      // init-time scratch (R3/c3 partials)

    int tid = threadIdx.x;

    // ---- constants ----
    if (tid < HID) {
        CON[0   + tid] = b0[tid];
        CON[128 + tid] = b1[tid];
        CON[256 + tid] = b2[tid];
        PRT[384 + tid] = Wout[tid] * b3[tid];  // c3 partial
    }
    if (tid < NS) {
        float m = safe_m[tid], lo = safe_l[tid];
        CON[512 + tid] = 0.5f * (m + lo);
        CON[528 + tid] = 2.0f / (m - lo);
    }
    // ---- R3 partials: 3 slices x 128 threads (short chains, coalesced) ----
    if (tid < 384) {
        int h = tid & 127, sl = tid >> 7;
        int j0 = (sl * HID) / 3, j1 = ((sl + 1) * HID) / 3;
        float acc = 0.f;
#pragma unroll 4
        for (int j = j0; j < j1; ++j) acc = fmaf(Wout[j], W3[j*HID + h], acc);
        PRT[sl*128 + h] = acc;
    }

    // ---- build W1/W2 fragments directly from global (L2-broadcast) ----
    for (int e = tid; e < 128*32; e += THREADS) {
        int T = e >> 5, lf = e & 31;
        int kt = T >> 4, nt = T & 15, qf = lf & 3, gf = lf >> 2;
        int n = 8*nt + gf, k = 16*kt + 2*qf;
        {
            float2 wlo = *(const float2*)&W1[n*HID + k];
            float2 whi = *(const float2*)&W1[n*HID + k + 8];
            uint2 uf; uf.x = f2h2(wlo.x, wlo.y); uf.y = f2h2(whi.x, whi.y);
            uint2 ub;
            ub.x = f2h2(W1[k*HID + n],     W1[(k+1)*HID + n]);
            ub.y = f2h2(W1[(k+8)*HID + n], W1[(k+9)*HID + n]);
            W1F[e] = uf; W1B[e] = ub;
        }
        {
            float2 wlo = *(const float2*)&W2[n*HID + k];
            float2 whi = *(const float2*)&W2[n*HID + k + 8];
            uint2 uf; uf.x = f2h2(wlo.x, wlo.y); uf.y = f2h2(whi.x, whi.y);
            uint2 ub;
            ub.x = f2h2(W2[k*HID + n],     W2[(k+1)*HID + n]);
            ub.y = f2h2(W2[(k+8)*HID + n], W2[(k+9)*HID + n]);
            W2F[e] = uf; W2B[e] = ub;
        }
    }
    for (int e = tid; e < 16*32; e += THREADS) {
        int T = e >> 5, lf = e & 31, qf = lf & 3, gf = lf >> 2;
        {   // W0F: fwd GEMM0, T = nt
            int n = 8*T + gf, k = 2*qf;
            uint2 u;
            u.x = f2h2(W0[n*NS + k], W0[n*NS + k + 1]);
            u.y = (qf < 2) ? f2h2(W0[n*NS + k + 8], W0[n*NS + k + 9]) : 0u;
            W0F[e] = u;
        }
        {   // W0B: final J, kt=T>>1, nt=T&1
            int kt = T >> 1, ntb = T & 1;
            int n = 8*ntb + gf, k = 16*kt + 2*qf;
            float w00 = 0.f, w01 = 0.f, w10 = 0.f, w11 = 0.f;
            if (n < NS) {
                w00 = W0[k*NS + n];     w01 = W0[(k+1)*NS + n];
                w10 = W0[(k+8)*NS + n]; w11 = W0[(k+9)*NS + n];
            }
            uint2 u; u.x = f2h2(w00, w01); u.y = f2h2(w10, w11);
            W0B[e] = u;
        }
    }
    __syncthreads();
    // combine R3 partials; c3 reduce
    if (tid < HID)
        CON[384 + tid] = PRT[tid] + PRT[128 + tid] + PRT[256 + tid];
    if (tid == 0) {
        float c = bout[0];
#pragma unroll 4
        for (int i = 0; i < HID; i += 4) {
            float4 p = *(const float4*)&PRT[384 + i];
            c += p.x + p.y + p.z + p.w;
        }
        CON[544] = c;
    }
    __syncthreads();

    int w = tid >> 5, l = tid & 31, q = l & 3, g = l >> 2;
    int pair = w >> 1, wa = w & 1;
    char* PB = smem + OFF_PB + pair*PBSTRIDE;
    uint2* ACTa = (uint2*)PB;             // [16 nt][32 lanes]
    uint2* ACTb = (uint2*)(PB + 4096);
    float* VX   = (float*)(PB + 8192);
    int barid = pair + 1;

    const float* B0S = CON;
    const float* B1S = CON + 128;
    const float* B2S = CON + 256;
    const float* R3S = CON + 384;
    const float* CENS = CON + 512;
    const float* INVS = CON + 528;

    int nt0 = 8*wa;                       // this warp's n-tile half

    int ntask = (nb + MROWS - 1) / MROWS;
    for (int task = blockIdx.x + GRID*pair; task < ntask; task += GRID*PAIRS) {
        int base = task * MROWS;
        int ra = base + g, rb = base + g + 8;
        bool oka = ra < nb, okb = rb < nb;

        u32 A[32];
        u32 V0k[16], V1k[16];             // own-half V0/V1 (fp16 pairs), register-resident
        float c[8][4];

        // ---- X load + normalize -> A[0..3] ----
        {
            float2 z2 = make_float2(0.f, 0.f);
            float2 xa = oka ? *(const float2*)&state[ra*NS + 2*q] : z2;
            float2 xb = okb ? *(const float2*)&state[rb*NS + 2*q] : z2;
            float2 xc = z2, xd = z2;
            float c0v = CENS[2*q], c1v = CENS[2*q+1];
            float i0v = INVS[2*q], i1v = INVS[2*q+1];
            xa.x = (xa.x - c0v)*i0v; xa.y = (xa.y - c1v)*i1v;
            xb.x = (xb.x - c0v)*i0v; xb.y = (xb.y - c1v)*i1v;
            if (q < 2) {
                if (oka) xc = *(const float2*)&state[ra*NS + 2*q + 8];
                if (okb) xd = *(const float2*)&state[rb*NS + 2*q + 8];
                float c2v = CENS[2*q+8], c3v = CENS[2*q+9];
                float i2v = INVS[2*q+8], i3v = INVS[2*q+9];
                xc.x = (xc.x - c2v)*i2v; xc.y = (xc.y - c3v)*i3v;
                xd.x = (xd.x - c2v)*i2v; xd.y = (xd.y - c3v)*i3v;
            }
            A[0] = f2h2(xa.x, xa.y);
            A[1] = f2h2(xb.x, xb.y);
            A[2] = f2h2(xc.x, xc.y);
            A[3] = f2h2(xd.x, xd.y);
        }

        // ---- G0: V0 = tanh(X*W0^T + b0) -> ACTa + V0k ----
#pragma unroll
        for (int i = 0; i < 8; ++i) {
            int nt = nt0 + i;
            float2 bp = *(const float2*)&B0S[8*nt + 2*q];
            c[i][0] = bp.x; c[i][1] = bp.y; c[i][2] = bp.x; c[i][3] = bp.y;
            mma16816(c[i], &A[0], W0F[nt*32 + l]);
        }
#pragma unroll
        for (int i = 0; i < 8; ++i) {
            uint2 u;
            u.x = f2h2(ftanh(c[i][0]), ftanh(c[i][1]));
            u.y = f2h2(ftanh(c[i][2]), ftanh(c[i][3]));
            ACTa[(nt0 + i)*32 + l] = u;
            V0k[2*i] = u.x; V0k[2*i+1] = u.y;
        }
        bar_pair(barid);                             // (1) ACTa complete

        // ---- G1: V1 = tanh(V0*W1^T + b1): read a -> write b + V1k ----
#pragma unroll
        for (int j = 0; j < 16; ++j) {
            uint2 v = ACTa[j*32 + l];
            A[2*j] = v.x; A[2*j+1] = v.y;
        }
#pragma unroll
        for (int i = 0; i < 8; ++i) {
            float2 bp = *(const float2*)&B1S[8*(nt0+i) + 2*q];
            c[i][0] = bp.x; c[i][1] = bp.y; c[i][2] = bp.x; c[i][3] = bp.y;
        }
#pragma unroll
        for (int kt = 0; kt < 8; ++kt)
#pragma unroll
            for (int i = 0; i < 8; ++i)
                mma16816(c[i], &A[kt*4], W1F[(kt*16 + nt0 + i)*32 + l]);
#pragma unroll
        for (int i = 0; i < 8; ++i) {
            uint2 u;
            u.x = f2h2(ftanh(c[i][0]), ftanh(c[i][1]));
            u.y = f2h2(ftanh(c[i][2]), ftanh(c[i][3]));
            ACTb[(nt0 + i)*32 + l] = u;
            V1k[2*i] = u.x; V1k[2*i+1] = u.y;
        }
        bar_pair(barid);                             // (2) ACTb complete

        // ---- G2: V2 = tanh(V1*W2^T + b2); vout partial; g2: read b -> write a ----
#pragma unroll
        for (int j = 0; j < 16; ++j) {
            uint2 v = ACTb[j*32 + l];
            A[2*j] = v.x; A[2*j+1] = v.y;
        }
#pragma unroll
        for (int i = 0; i < 8; ++i) {
            float2 bp = *(const float2*)&B2S[8*(nt0+i) + 2*q];
            c[i][0] = bp.x; c[i][1] = bp.y; c[i][2] = bp.x; c[i][3] = bp.y;
        }
#pragma unroll
        for (int kt = 0; kt < 8; ++kt)
#pragma unroll
            for (int i = 0; i < 8; ++i)
                mma16816(c[i], &A[kt*4], W2F[(kt*16 + nt0 + i)*32 + l]);
        float vg = 0.f, vg8 = 0.f;
#pragma unroll
        for (int i = 0; i < 8; ++i) {
            int nt = nt0 + i;
            float2 r3p = *(const float2*)&R3S[8*nt + 2*q];
            float t0 = ftanh(c[i][0]), t1 = ftanh(c[i][1]);
            float t2 = ftanh(c[i][2]), t3 = ftanh(c[i][3]);
            vg  += r3p.x*t0 + r3p.y*t1;
            vg8 += r3p.x*t2 + r3p.y*t3;
            uint2 u;
            u.x = f2h2(r3p.x*(1.f - t0*t0), r3p.y*(1.f - t1*t1));
            u.y = f2h2(r3p.x*(1.f - t2*t2), r3p.y*(1.f - t3*t3));
            ACTa[nt*32 + l] = u;
        }
        vg  += __shfl_xor_sync(0xffffffffu, vg, 1);
        vg  += __shfl_xor_sync(0xffffffffu, vg, 2);
        vg8 += __shfl_xor_sync(0xffffffffu, vg8, 1);
        vg8 += __shfl_xor_sync(0xffffffffu, vg8, 2);
        if (wa == 1 && q == 0) { VX[g] = vg; VX[8+g] = vg8; }
        bar_pair(barid);                             // (3) g2 + VX complete
        if (wa == 0 && q == 0) {
            float c3 = CON[544];
            if (oka) out[ra*13] = vg + VX[g] + c3;
            if (okb) out[rb*13] = vg8 + VX[8+g] + c3;
        }

        // ---- B2: r1 = g2*W2 ; g1 = r1*(1-V1^2): read a -> write b ----
#pragma unroll
        for (int j = 0; j < 16; ++j) {
            uint2 v = ACTa[j*32 + l];
            A[2*j] = v.x; A[2*j+1] = v.y;
        }
#pragma unroll
        for (int i = 0; i < 8; ++i) { c[i][0]=0.f; c[i][1]=0.f; c[i][2]=0.f; c[i][3]=0.f; }
#pragma unroll
        for (int kt = 0; kt < 8; ++kt)
#pragma unroll
            for (int i = 0; i < 8; ++i)
                mma16816(c[i], &A[kt*4], W2B[(kt*16 + nt0 + i)*32 + l]);
#pragma unroll
        for (int i = 0; i < 8; ++i) {
            float2 va = h22f2(V1k[2*i]), vb = h22f2(V1k[2*i+1]);
            uint2 u;
            u.x = f2h2(c[i][0]*(1.f - va.x*va.x), c[i][1]*(1.f - va.y*va.y));
            u.y = f2h2(c[i][2]*(1.f - vb.x*vb.x), c[i][3]*(1.f - vb.y*vb.y));
            ACTb[(nt0 + i)*32 + l] = u;
        }
        bar_pair(barid);                             // (4) g1 complete

        // ---- B1: r0 = g1*W1 ; g0 = r0*(1-V0^2): read b -> write a ----
#pragma unroll
        for (int j = 0; j < 16; ++j) {
            uint2 v = ACTb[j*32 + l];
            A[2*j] = v.x; A[2*j+1] = v.y;
        }
#pragma unroll
        for (int i = 0; i < 8; ++i) { c[i][0]=0.f; c[i][1]=0.f; c[i][2]=0.f; c[i][3]=0.f; }
#pragma unroll
        for (int kt = 0; kt < 8; ++kt)
#pragma unroll
            for (int i = 0; i < 8; ++i)
                mma16816(c[i], &A[kt*4], W1B[(kt*16 + nt0 + i)*32 + l]);
#pragma unroll
        for (int i = 0; i < 8; ++i) {
            float2 va = h22f2(V0k[2*i]), vb = h22f2(V0k[2*i+1]);
            uint2 u;
            u.x = f2h2(c[i][0]*(1.f - va.x*va.x), c[i][1]*(1.f - va.y*va.y));
            u.y = f2h2(c[i][2]*(1.f - vb.x*vb.x), c[i][3]*(1.f - vb.y*vb.y));
            ACTa[(nt0 + i)*32 + l] = u;
        }
        bar_pair(barid);                             // (5) g0 complete

        // ---- J: g0*W0 -> [16x12]; warp wa does n-tile wa: read a ----
#pragma unroll
        for (int j = 0; j < 16; ++j) {
            uint2 v = ACTa[j*32 + l];
            A[2*j] = v.x; A[2*j+1] = v.y;
        }
        {
            float cj[4] = {0.f, 0.f, 0.f, 0.f};
#pragma unroll
            for (int kt = 0; kt < 8; ++kt)
                mma16816(cj, &A[kt*4], W0B[(kt*2 + wa)*32 + l]);
            int cb = 8*wa + 2*q;
            if (cb < NS) {
                float iv0 = INVS[cb], iv1 = INVS[cb+1];
                if (oka) {
                    out[ra*13 + 1 + cb]     = cj[0]*iv0;
                    out[ra*13 + 1 + cb + 1] = cj[1]*iv1;
                }
                if (okb) {
                    out[rb*13 + 1 + cb]     = cj[2]*iv0;
                    out[rb*13 + 1 + cb + 1] = cj[3]*iv1;
                }
            }
        }
        bar_pair(barid);                             // (6) J reads done before next G0
    }
}

extern "C" void kernel_launch(void* const* d_in, const int* in_sizes, int n_in,
                              void* d_out, int out_size)
{
    const float* state  = (const float*)d_in[0];
    const float* safe_m = (const float*)d_in[1];
    const float* safe_l = (const float*)d_in[2];
    const float* W0     = (const float*)d_in[3];
    const float* b0     = (const float*)d_in[4];
    const float* W1     = (const float*)d_in[5];
    const float* b1     = (const float*)d_in[6];
    const float* W2     = (const float*)d_in[7];
    const float* b2     = (const float*)d_in[8];
    const float* W3     = (const float*)d_in[9];
    const float* b3     = (const float*)d_in[10];
    const float* Wout   = (const float*)d_in[11];
    const float* bout   = (const float*)d_in[12];
    float* out = (float*)d_out;

    int nb = in_sizes[0] / NS;

    cudaFuncSetAttribute(mlp_kernel, cudaFuncAttributeMaxDynamicSharedMemorySize,
                         SMEM_BYTES);

    mlp_kernel<<<GRID, THREADS, SMEM_BYTES>>>(
        state, safe_m, safe_l, W0, b0, W1, b1, W2, b2, W3, b3, Wout, bout,
        out, nb);
}